// round 9
// baseline (speedup 1.0000x reference)
#include <cuda_runtime.h>
#include <cuda_bf16.h>
#include <math.h>
#include <stdint.h>

typedef __nv_bfloat16 bf16;
typedef __nv_bfloat162 bf162;

// ---------------- problem constants ----------------
#define Bb 4
#define Cc 512
#define NN 4096
#define GG 32
#define CPG 16

// ---------------- scratch (device globals) ----------------
__device__ __align__(128) bf16  g_h16  [(size_t)Bb*NN*Cc];    // [B,N,C] GN out
__device__ __align__(128) bf16  g_qk16 [(size_t)Bb*NN*2*Cc];  // [B,N,2C] q|k
__device__ __align__(128) bf16  g_v16  [(size_t)Bb*Cc*NN];    // [B,C,N]
__device__ __align__(128) bf16  g_ao16 [(size_t)Bb*NN*Cc];    // [B,N,C]
__device__ __align__(128) float g_s    [(size_t)Bb*NN*NN];    // [B,N,N] scores fp32
__device__ __align__(128) bf16  g_a16  [(size_t)Bb*NN*NN];    // [B,N,N] attn bf16
__device__ __align__(128) bf16  g_w16  [4*Cc*Cc];             // wq|wk|wv|wo
__device__ __align__(128) float g_bqk  [2*Cc];                // bq|bk

// ---------------- helpers ----------------
__device__ __forceinline__ uint32_t smem_u32(const void* p) {
    uint32_t a;
    asm("{ .reg .u64 t; cvta.to.shared.u64 t, %1; cvt.u32.u64 %0, t; }" : "=r"(a) : "l"(p));
    return a;
}
__device__ __forceinline__ void mma_bf16(float* c, const uint32_t* a, const uint32_t* b) {
    asm volatile("mma.sync.aligned.m16n8k16.row.col.f32.bf16.bf16.f32 "
        "{%0,%1,%2,%3}, {%4,%5,%6,%7}, {%8,%9}, {%0,%1,%2,%3};"
        : "+f"(c[0]), "+f"(c[1]), "+f"(c[2]), "+f"(c[3])
        : "r"(a[0]), "r"(a[1]), "r"(a[2]), "r"(a[3]), "r"(b[0]), "r"(b[1]));
}
__device__ __forceinline__ void ldmatrix_x4(uint32_t* r, uint32_t addr) {
    asm volatile("ldmatrix.sync.aligned.m8n8.x4.shared.b16 {%0,%1,%2,%3}, [%4];"
        : "=r"(r[0]), "=r"(r[1]), "=r"(r[2]), "=r"(r[3]) : "r"(addr));
}

// ---------------- block reductions ----------------
__device__ __forceinline__ float block_sum(float v, float* sh) {
    int lane = threadIdx.x & 31, w = threadIdx.x >> 5;
    #pragma unroll
    for (int o = 16; o; o >>= 1) v += __shfl_down_sync(0xffffffffu, v, o);
    if (!lane) sh[w] = v;
    __syncthreads();
    int nw = blockDim.x >> 5;
    v = (threadIdx.x < nw) ? sh[threadIdx.x] : 0.f;
    if (w == 0) {
        #pragma unroll
        for (int o = 16; o; o >>= 1) v += __shfl_down_sync(0xffffffffu, v, o);
        if (!lane) sh[0] = v;
    }
    __syncthreads();
    float r = sh[0]; __syncthreads(); return r;
}
__device__ __forceinline__ float block_max(float v, float* sh) {
    int lane = threadIdx.x & 31, w = threadIdx.x >> 5;
    #pragma unroll
    for (int o = 16; o; o >>= 1) v = fmaxf(v, __shfl_down_sync(0xffffffffu, v, o));
    if (!lane) sh[w] = v;
    __syncthreads();
    int nw = blockDim.x >> 5;
    v = (threadIdx.x < nw) ? sh[threadIdx.x] : -INFINITY;
    if (w == 0) {
        #pragma unroll
        for (int o = 16; o; o >>= 1) v = fmaxf(v, __shfl_down_sync(0xffffffffu, v, o));
        if (!lane) sh[0] = v;
    }
    __syncthreads();
    float r = sh[0]; __syncthreads(); return r;
}

// ---------------- GroupNorm -> token-major bf16 hT --------------
__global__ __launch_bounds__(256) void groupnorm_kernel(
    const float* __restrict__ x, const float* __restrict__ gamma,
    const float* __restrict__ beta, bf16* __restrict__ hT)
{
    __shared__ float sh[32];
    int b = blockIdx.x / GG, g = blockIdx.x % GG;
    const size_t base = ((size_t)b * Cc + (size_t)g * CPG) * NN;
    const long len = (long)CPG * NN;

    float s = 0.f, ss = 0.f;
    for (long i = threadIdx.x; i < len; i += 256) {
        float v = x[base + i]; s += v; ss += v * v;
    }
    s  = block_sum(s,  sh);
    ss = block_sum(ss, sh);
    float mean = s / (float)len;
    float var  = ss / (float)len - mean * mean;
    float inv  = rsqrtf(var + 1e-6f);

    float gm[CPG], bt[CPG];
    #pragma unroll
    for (int c = 0; c < CPG; c++) { gm[c] = gamma[g*CPG+c] * inv; bt[c] = beta[g*CPG+c]; }

    for (int i = threadIdx.x; i < NN; i += 256) {
        bf162 vals[CPG/2];
        #pragma unroll
        for (int c = 0; c < CPG; c += 2) {
            float a = (x[base + (size_t)c*NN + i] - mean) * gm[c] + bt[c];
            float b2 = (x[base + (size_t)(c+1)*NN + i] - mean) * gm[c+1] + bt[c+1];
            vals[c/2] = __floats2bfloat162_rn(a, b2);
        }
        bf16* dst = hT + ((size_t)b*NN + i) * Cc + g*CPG;
        #pragma unroll
        for (int q = 0; q < CPG/8; q++)
            ((float4*)dst)[q] = *(float4*)&vals[q*4];
    }
}

// ---------------- weight convert + bias concat ----------------
__global__ __launch_bounds__(256) void round_w_kernel(
    const float* __restrict__ a, const float* __restrict__ b,
    const float* __restrict__ c, const float* __restrict__ d,
    bf16* __restrict__ o)
{
    int i = blockIdx.x * 256 + threadIdx.x;
    int w = i >> 18, j = i & 0x3FFFF;
    const float* src = (w == 0) ? a : (w == 1) ? b : (w == 2) ? c : d;
    o[i] = __float2bfloat16_rn(src[j]);
}
__global__ __launch_bounds__(256) void concat_bias_kernel(
    const float* __restrict__ a, const float* __restrict__ b, float* __restrict__ o)
{
    int i = blockIdx.x * 256 + threadIdx.x;
    o[i] = (i < Cc) ? a[i] : b[i - Cc];
}

// ---------------- softmax: fp32 scores in -> bf16 attn out -------------
__global__ __launch_bounds__(256) void softmax_kernel(
    const float* __restrict__ s, bf16* __restrict__ a)
{
    __shared__ float sh[32];
    const float* p = s + (size_t)blockIdx.x * NN;
    bf16* pa = a + (size_t)blockIdx.x * NN;
    float v[16];
    #pragma unroll
    for (int t = 0; t < 16; t++) v[t] = p[threadIdx.x + t*256];
    float m = -INFINITY;
    #pragma unroll
    for (int t = 0; t < 16; t++) m = fmaxf(m, v[t]);
    m = block_max(m, sh);
    float sum = 0.f;
    #pragma unroll
    for (int t = 0; t < 16; t++) { v[t] = __expf(v[t] - m); sum += v[t]; }
    sum = block_sum(sum, sh);
    float inv = 1.f / sum;
    #pragma unroll
    for (int t = 0; t < 16; t++) pa[threadIdx.x + t*256] = __float2bfloat16_rn(v[t] * inv);
}

// ---------------- bf16 mma.sync GEMM: D[m,n] = Σk A[m,k] B[n,k] ----------
// CTA tile 128x128x64(bf16), 128 threads, warp grid 2(M)x2(N), warp tile 64x64.
// LDS:HMMA balanced (64KB per 1M MACs). ldmatrix.x4 + kk double-buffer,
// single barrier per kt, 3-stage cp.async, 2 CTAs/SM.
// EPI: 0 = +bias[n] -> bf16   (merged QK proj)
//      1 = +bias[m] -> bf16   (V proj)
//      2 = *alpha  -> fp32    (scores)
//      3 = -> bf16            (attn*V)
//      4 = +bias[m]+res fp32  (output proj + residual)
#define BM 128
#define BN 128
#define BK 64
#define THREADS 128
#define STAGES 3
#define SROW 72                       // bf16 per smem row (144B, conflict-free ldmatrix)
#define ATILE_H (BM * SROW)
#define BTILE_H (BN * SROW)
#define STAGE_H (ATILE_H + BTILE_H)
#define STAGE_BYTES (STAGE_H * 2)
#define SMEM_REQ (STAGES * STAGE_BYTES)

template<int ROWS>
__device__ __forceinline__ void load_tile(const bf16* g, bf16* s, int tid, int ld) {
    int ch = tid & 7;                 // 8 x 16B chunks per 64-bf16 row
    int r0 = tid >> 3;                // 16 rows per pass
    #pragma unroll
    for (int i = 0; i < ROWS / 16; i++) {
        int r = r0 + i * 16;
        uint32_t dst = smem_u32(s + r * SROW + ch * 8);
        const bf16* src = g + (size_t)r * ld + ch * 8;
        asm volatile("cp.async.cg.shared.global [%0], [%1], 16;" :: "r"(dst), "l"(src));
    }
}

template<int EPI>
__global__ __launch_bounds__(THREADS, 2) void mma_gemm(
    const bf16* __restrict__ A, long zA, int ldA,
    const bf16* __restrict__ B, long zB, int ldB,
    const float* __restrict__ bias,
    const float* __restrict__ res, long zR,
    void* __restrict__ Cout, long zC, int ldC,
    int K, float alpha)
{
    constexpr bool OUT_BF = (EPI == 0 || EPI == 1 || EPI == 3);
    extern __shared__ bf16 smem[];

    const int tid = threadIdx.x;
    const int m0 = blockIdx.y * BM, n0 = blockIdx.x * BN, bz = blockIdx.z;

    A += (size_t)bz * zA + (size_t)m0 * ldA;
    B += (size_t)bz * zB + (size_t)n0 * ldB;

    const int KT = K / BK;

    #pragma unroll
    for (int st = 0; st < STAGES - 1; st++) {
        load_tile<BM>(A + st * BK, smem + st * STAGE_H, tid, ldA);
        load_tile<BN>(B + st * BK, smem + st * STAGE_H + ATILE_H, tid, ldB);
        asm volatile("cp.async.commit_group;" ::: "memory");
    }

    const int lane = tid & 31, wid = tid >> 5;
    const int gid = lane >> 2, tig = lane & 3;
    const int wm = (wid & 1) * 64;     // warp M offset (2 warps)
    const int wn = (wid >> 1) * 64;    // warp N offset (2 warps)

    const uint32_t sbase = smem_u32(smem);
    // A ldmatrix map: lanes 0-15 rows, lanes 16-31 rows @k+8
    const uint32_t a_off = ((wm + (lane & 15)) * SROW + ((lane >> 4) * 8)) * 2;
    // B ldmatrix map: n = (l&7) + ((l>>4)<<3), k = ((l>>3)&1)*8
    const uint32_t b_off = (ATILE_H + (wn + (lane & 7) + ((lane >> 4) << 3)) * SROW
                            + (((lane >> 3) & 1) * 8)) * 2;

    float c[4][8][4];
    #pragma unroll
    for (int im = 0; im < 4; im++)
        #pragma unroll
        for (int in = 0; in < 8; in++)
            #pragma unroll
            for (int r = 0; r < 4; r++) c[im][in][r] = 0.f;

    uint32_t af[2][4][4], bq[2][4][4];

    for (int kt = 0; kt < KT; kt++) {
        asm volatile("cp.async.wait_group %0;" :: "n"(STAGES - 2) : "memory");
        __syncthreads();   // single barrier per kt

        if (kt + STAGES - 1 < KT) {
            int st = (kt + STAGES - 1) % STAGES;
            load_tile<BM>(A + (kt + STAGES - 1) * BK, smem + st * STAGE_H, tid, ldA);
            load_tile<BN>(B + (kt + STAGES - 1) * BK, smem + st * STAGE_H + ATILE_H, tid, ldB);
        }
        asm volatile("cp.async.commit_group;" ::: "memory");

        const uint32_t stb = sbase + (kt % STAGES) * STAGE_BYTES;

        // prefetch kk=0 fragments
        #pragma unroll
        for (int im = 0; im < 4; im++)
            ldmatrix_x4(af[0][im], stb + a_off + im * (16 * SROW * 2));
        #pragma unroll
        for (int ib = 0; ib < 4; ib++)
            ldmatrix_x4(bq[0][ib], stb + b_off + ib * (16 * SROW * 2));

        #pragma unroll
        for (int kk = 0; kk < 4; kk++) {          // 4 x k16 per BK=64
            int cur = kk & 1, nxt = cur ^ 1;
            if (kk < 3) {
                const uint32_t ka = stb + (kk + 1) * 32;
                #pragma unroll
                for (int im = 0; im < 4; im++)
                    ldmatrix_x4(af[nxt][im], ka + a_off + im * (16 * SROW * 2));
                #pragma unroll
                for (int ib = 0; ib < 4; ib++)
                    ldmatrix_x4(bq[nxt][ib], ka + b_off + ib * (16 * SROW * 2));
            }
            #pragma unroll
            for (int im = 0; im < 4; im++)
                #pragma unroll
                for (int in = 0; in < 8; in++)
                    mma_bf16(c[im][in], af[cur][im], &bq[cur][in >> 1][(in & 1) * 2]);
        }
    }

    // ---- epilogue ----
    #pragma unroll
    for (int im = 0; im < 4; im++) {
        int r0 = im * 16 + gid;
        float bm0 = 0.f, bm1 = 0.f;
        if (EPI == 1 || EPI == 4) {
            bm0 = __ldg(bias + m0 + wm + r0);
            bm1 = __ldg(bias + m0 + wm + r0 + 8);
        }
        #pragma unroll
        for (int in = 0; in < 8; in++) {
            int col = in * 8 + tig * 2;
            float v0 = c[im][in][0], v1 = c[im][in][1];
            float v2 = c[im][in][2], v3 = c[im][in][3];
            if (EPI == 0) {
                float bn0 = __ldg(bias + n0 + wn + col);
                float bn1 = __ldg(bias + n0 + wn + col + 1);
                v0 += bn0; v1 += bn1; v2 += bn0; v3 += bn1;
            } else if (EPI == 1) {
                v0 += bm0; v1 += bm0; v2 += bm1; v3 += bm1;
            } else if (EPI == 2) {
                v0 *= alpha; v1 *= alpha; v2 *= alpha; v3 *= alpha;
            } else if (EPI == 4) {
                const float* ra = res + (size_t)bz * zR + (size_t)(m0 + wm + r0) * ldC + n0 + wn + col;
                const float* rb = res + (size_t)bz * zR + (size_t)(m0 + wm + r0 + 8) * ldC + n0 + wn + col;
                v0 += bm0 + ra[0]; v1 += bm0 + ra[1];
                v2 += bm1 + rb[0]; v3 += bm1 + rb[1];
            }
            if (OUT_BF) {
                bf16* Cb = (bf16*)Cout + (size_t)bz * zC + (size_t)(m0 + wm + r0) * ldC + n0 + wn + col;
                bf16* Cb2 = (bf16*)Cout + (size_t)bz * zC + (size_t)(m0 + wm + r0 + 8) * ldC + n0 + wn + col;
                *(bf162*)Cb  = __floats2bfloat162_rn(v0, v1);
                *(bf162*)Cb2 = __floats2bfloat162_rn(v2, v3);
            } else {
                float* Cf = (float*)Cout + (size_t)bz * zC + (size_t)(m0 + wm + r0) * ldC + n0 + wn + col;
                float* Cf2 = (float*)Cout + (size_t)bz * zC + (size_t)(m0 + wm + r0 + 8) * ldC + n0 + wn + col;
                *(float2*)Cf  = make_float2(v0, v1);
                *(float2*)Cf2 = make_float2(v2, v3);
            }
        }
    }
}

// ---------------- launch ----------------
extern "C" void kernel_launch(void* const* d_in, const int* in_sizes, int n_in,
                              void* d_out, int out_size)
{
    const float* x     = (const float*)d_in[0];
    const float* gamma = (const float*)d_in[1];
    const float* beta  = (const float*)d_in[2];
    const float* wq    = (const float*)d_in[3];
    const float* bq    = (const float*)d_in[4];
    const float* wk    = (const float*)d_in[5];
    const float* bk    = (const float*)d_in[6];
    const float* wv    = (const float*)d_in[7];
    const float* bv    = (const float*)d_in[8];
    const float* wo    = (const float*)d_in[9];
    const float* bo    = (const float*)d_in[10];
    float* out = (float*)d_out;

    bf16 *h16, *qk16, *v16, *ao16, *a16, *w16;
    float *s, *bqk;
    cudaGetSymbolAddress((void**)&h16,  g_h16);
    cudaGetSymbolAddress((void**)&qk16, g_qk16);
    cudaGetSymbolAddress((void**)&v16,  g_v16);
    cudaGetSymbolAddress((void**)&ao16, g_ao16);
    cudaGetSymbolAddress((void**)&a16,  g_a16);
    cudaGetSymbolAddress((void**)&w16,  g_w16);
    cudaGetSymbolAddress((void**)&s,    g_s);
    cudaGetSymbolAddress((void**)&bqk,  g_bqk);

    static bool attr_done = false;
    if (!attr_done) {
        cudaFuncSetAttribute(mma_gemm<0>, cudaFuncAttributeMaxDynamicSharedMemorySize, SMEM_REQ);
        cudaFuncSetAttribute(mma_gemm<1>, cudaFuncAttributeMaxDynamicSharedMemorySize, SMEM_REQ);
        cudaFuncSetAttribute(mma_gemm<2>, cudaFuncAttributeMaxDynamicSharedMemorySize, SMEM_REQ);
        cudaFuncSetAttribute(mma_gemm<3>, cudaFuncAttributeMaxDynamicSharedMemorySize, SMEM_REQ);
        cudaFuncSetAttribute(mma_gemm<4>, cudaFuncAttributeMaxDynamicSharedMemorySize, SMEM_REQ);
        attr_done = true;
    }

    const long CN  = (long)Cc * NN;      // [C,N] batch stride
    const long NC  = (long)NN * Cc;      // [N,C] batch stride
    const long NC2 = (long)NN * 2 * Cc;  // [N,2C] batch stride
    const long NN2 = (long)NN * NN;
    const float scale = 1.0f / sqrtf((float)Cc);

    // 1) GroupNorm -> h16 [B,N,C]
    groupnorm_kernel<<<Bb * GG, 256>>>(x, gamma, beta, h16);
    // 2) weights -> bf16, concat q/k biases
    round_w_kernel<<<4 * Cc * Cc / 256, 256>>>(wq, wk, wv, wo, w16);
    concat_bias_kernel<<<2 * Cc / 256, 256>>>(bq, bk, bqk);

    // 3) merged QK proj
    mma_gemm<0><<<dim3(2*Cc/BN, NN/BM, Bb), THREADS, SMEM_REQ>>>(
        h16, NC, Cc, w16, 0, Cc, bqk, nullptr, 0, qk16, NC2, 2*Cc, Cc, 0.f);
    // 4) V proj
    mma_gemm<1><<<dim3(NN/BN, Cc/BM, Bb), THREADS, SMEM_REQ>>>(
        w16 + 2*Cc*Cc, 0, Cc, h16, NC, Cc, bv, nullptr, 0, v16, CN, NN, Cc, 0.f);
    // 5) scores
    mma_gemm<2><<<dim3(NN/BN, NN/BM, Bb), THREADS, SMEM_REQ>>>(
        qk16, NC2, 2*Cc, qk16 + Cc, NC2, 2*Cc, nullptr, nullptr, 0, s, NN2, NN, Cc, scale);
    // 6) softmax
    softmax_kernel<<<Bb * NN, 256>>>(s, a16);
    // 7) attn * V
    mma_gemm<3><<<dim3(Cc/BN, NN/BM, Bb), THREADS, SMEM_REQ>>>(
        a16, NN2, NN, v16, CN, NN, nullptr, nullptr, 0, ao16, NC, Cc, NN, 0.f);
    // 8) output proj + residual
    mma_gemm<4><<<dim3(NN/BN, Cc/BM, Bb), THREADS, SMEM_REQ>>>(
        w16 + 3*Cc*Cc, 0, Cc, ao16, NC, Cc, bo, x, CN, out, CN, NN, Cc, 0.f);
}

// round 10
// speedup vs baseline: 1.0220x; 1.0220x over previous
#include <cuda_runtime.h>
#include <cuda_bf16.h>
#include <math.h>
#include <stdint.h>

typedef __nv_bfloat16 bf16;
typedef __nv_bfloat162 bf162;

// ---------------- problem constants ----------------
#define Bb 4
#define Cc 512
#define NN 4096
#define GG 32
#define CPG 16

// ---------------- scratch (device globals) ----------------
__device__ __align__(128) bf16  g_h16  [(size_t)Bb*NN*Cc];    // [B,N,C] GN out
__device__ __align__(128) bf16  g_qk16 [(size_t)Bb*NN*2*Cc];  // [B,N,2C] q|k
__device__ __align__(128) bf16  g_v16  [(size_t)Bb*Cc*NN];    // [B,C,N]
__device__ __align__(128) bf16  g_ao16 [(size_t)Bb*NN*Cc];    // [B,N,C]
__device__ __align__(128) float g_s    [(size_t)Bb*NN*NN];    // [B,N,N] scores fp32
__device__ __align__(128) bf16  g_a16  [(size_t)Bb*NN*NN];    // [B,N,N] attn bf16
__device__ __align__(128) bf16  g_w16  [4*Cc*Cc];             // wq|wk|wv|wo
__device__ __align__(128) float g_bqk  [2*Cc];                // bq|bk
__device__ __align__(128) float2 g_part[Bb*GG*8];             // GN partial sums

// ---------------- helpers ----------------
__device__ __forceinline__ uint32_t smem_u32(const void* p) {
    uint32_t a;
    asm("{ .reg .u64 t; cvta.to.shared.u64 t, %1; cvt.u32.u64 %0, t; }" : "=r"(a) : "l"(p));
    return a;
}
__device__ __forceinline__ void mma_bf16(float* c, const uint32_t* a, const uint32_t* b) {
    asm volatile("mma.sync.aligned.m16n8k16.row.col.f32.bf16.bf16.f32 "
        "{%0,%1,%2,%3}, {%4,%5,%6,%7}, {%8,%9}, {%0,%1,%2,%3};"
        : "+f"(c[0]), "+f"(c[1]), "+f"(c[2]), "+f"(c[3])
        : "r"(a[0]), "r"(a[1]), "r"(a[2]), "r"(a[3]), "r"(b[0]), "r"(b[1]));
}
__device__ __forceinline__ void ldmatrix_x4(uint32_t* r, uint32_t addr) {
    asm volatile("ldmatrix.sync.aligned.m8n8.x4.shared.b16 {%0,%1,%2,%3}, [%4];"
        : "=r"(r[0]), "=r"(r[1]), "=r"(r[2]), "=r"(r[3]) : "r"(addr));
}

// ---------------- block reductions ----------------
__device__ __forceinline__ float block_sum(float v, float* sh) {
    int lane = threadIdx.x & 31, w = threadIdx.x >> 5;
    #pragma unroll
    for (int o = 16; o; o >>= 1) v += __shfl_down_sync(0xffffffffu, v, o);
    if (!lane) sh[w] = v;
    __syncthreads();
    int nw = blockDim.x >> 5;
    v = (threadIdx.x < nw) ? sh[threadIdx.x] : 0.f;
    if (w == 0) {
        #pragma unroll
        for (int o = 16; o; o >>= 1) v += __shfl_down_sync(0xffffffffu, v, o);
        if (!lane) sh[0] = v;
    }
    __syncthreads();
    float r = sh[0]; __syncthreads(); return r;
}
__device__ __forceinline__ float block_max(float v, float* sh) {
    int lane = threadIdx.x & 31, w = threadIdx.x >> 5;
    #pragma unroll
    for (int o = 16; o; o >>= 1) v = fmaxf(v, __shfl_down_sync(0xffffffffu, v, o));
    if (!lane) sh[w] = v;
    __syncthreads();
    int nw = blockDim.x >> 5;
    v = (threadIdx.x < nw) ? sh[threadIdx.x] : -INFINITY;
    if (w == 0) {
        #pragma unroll
        for (int o = 16; o; o >>= 1) v = fmaxf(v, __shfl_down_sync(0xffffffffu, v, o));
        if (!lane) sh[0] = v;
    }
    __syncthreads();
    float r = sh[0]; __syncthreads(); return r;
}

// ---------------- GroupNorm stage 1: partial sums --------------------------
// 8 partitions per (b,g) group, partitioned by token range. 1024 blocks.
__global__ __launch_bounds__(256) void gn_stats(
    const float* __restrict__ x, float2* __restrict__ partials)
{
    __shared__ float sh[32];
    int blk = blockIdx.x;
    int bg = blk >> 3, p = blk & 7;
    const size_t base = (size_t)bg * CPG * NN;   // groups are contiguous in [B*C]
    const int i0 = p * 512;

    float s = 0.f, ss = 0.f;
    #pragma unroll
    for (int c = 0; c < CPG; c++) {
        #pragma unroll
        for (int j = 0; j < 2; j++) {
            float v = x[base + (size_t)c * NN + i0 + threadIdx.x + j * 256];
            s += v; ss += v * v;
        }
    }
    s  = block_sum(s,  sh);
    ss = block_sum(ss, sh);
    if (threadIdx.x == 0) partials[blk] = make_float2(s, ss);
}

// ---------------- GroupNorm stage 2: normalize + transpose ----------------
// 1024 blocks; each handles 512 tokens x 16 channels of its group.
__global__ __launch_bounds__(256) void gn_norm(
    const float* __restrict__ x, const float2* __restrict__ partials,
    const float* __restrict__ gamma, const float* __restrict__ beta,
    bf16* __restrict__ hT)
{
    int blk = blockIdx.x;
    int bg = blk >> 3, p = blk & 7;
    int b = bg / GG, g = bg % GG;

    float s = 0.f, ss = 0.f;
    #pragma unroll
    for (int q = 0; q < 8; q++) {           // fixed order -> deterministic
        float2 pr = partials[bg * 8 + q];
        s += pr.x; ss += pr.y;
    }
    const float len = (float)(CPG * NN);
    float mean = s / len;
    float inv  = rsqrtf(ss / len - mean * mean + 1e-6f);

    float gm[CPG], bt[CPG];
    #pragma unroll
    for (int c = 0; c < CPG; c++) { gm[c] = gamma[g*CPG+c] * inv; bt[c] = beta[g*CPG+c]; }

    const size_t base = (size_t)bg * CPG * NN;
    #pragma unroll
    for (int j = 0; j < 2; j++) {
        int i = p * 512 + threadIdx.x + j * 256;
        bf162 vals[CPG/2];
        #pragma unroll
        for (int c = 0; c < CPG; c += 2) {
            float a  = (x[base + (size_t)c     * NN + i] - mean) * gm[c]   + bt[c];
            float b2 = (x[base + (size_t)(c+1) * NN + i] - mean) * gm[c+1] + bt[c+1];
            vals[c/2] = __floats2bfloat162_rn(a, b2);
        }
        bf16* dst = hT + ((size_t)b * NN + i) * Cc + g * CPG;
        #pragma unroll
        for (int q = 0; q < CPG/8; q++)
            ((float4*)dst)[q] = *(float4*)&vals[q*4];
    }
}

// ---------------- weight convert + bias concat ----------------
__global__ __launch_bounds__(256) void round_w_kernel(
    const float* __restrict__ a, const float* __restrict__ b,
    const float* __restrict__ c, const float* __restrict__ d,
    bf16* __restrict__ o)
{
    int i = blockIdx.x * 256 + threadIdx.x;
    int w = i >> 18, j = i & 0x3FFFF;
    const float* src = (w == 0) ? a : (w == 1) ? b : (w == 2) ? c : d;
    o[i] = __float2bfloat16_rn(src[j]);
}
__global__ __launch_bounds__(256) void concat_bias_kernel(
    const float* __restrict__ a, const float* __restrict__ b, float* __restrict__ o)
{
    int i = blockIdx.x * 256 + threadIdx.x;
    o[i] = (i < Cc) ? a[i] : b[i - Cc];
}

// ---------------- softmax: fp32 scores in -> bf16 attn out -------------
__global__ __launch_bounds__(256) void softmax_kernel(
    const float* __restrict__ s, bf16* __restrict__ a)
{
    __shared__ float sh[32];
    const float* p = s + (size_t)blockIdx.x * NN;
    bf16* pa = a + (size_t)blockIdx.x * NN;
    float v[16];
    #pragma unroll
    for (int t = 0; t < 16; t++) v[t] = p[threadIdx.x + t*256];
    float m = -INFINITY;
    #pragma unroll
    for (int t = 0; t < 16; t++) m = fmaxf(m, v[t]);
    m = block_max(m, sh);
    float sum = 0.f;
    #pragma unroll
    for (int t = 0; t < 16; t++) { v[t] = __expf(v[t] - m); sum += v[t]; }
    sum = block_sum(sum, sh);
    float inv = 1.f / sum;
    #pragma unroll
    for (int t = 0; t < 16; t++) pa[threadIdx.x + t*256] = __float2bfloat16_rn(v[t] * inv);
}

// ---------------- bf16 mma.sync GEMM: D[m,n] = Σk A[m,k] B[n,k] ----------
// Round-8 config: CTA 128x128x64, 256 threads, warps 2(M)x4(N), warp 64x32.
// ldmatrix.x4 + kk double-buffer, single barrier per kt, 3-stage cp.async,
// 2 CTAs/SM.
// EPI: 0 = +bias[n] -> bf16   (merged QK proj)
//      1 = +bias[m] -> bf16   (V proj)
//      2 = *alpha  -> fp32    (scores)
//      3 = -> bf16            (attn*V)
//      4 = +bias[m]+res fp32  (output proj + residual)
#define BM 128
#define BN 128
#define BK 64
#define STAGES 3
#define SROW 72                       // bf16 per smem row (144B, conflict-free)
#define ATILE_H (BM * SROW)
#define BTILE_H (BN * SROW)
#define STAGE_H (ATILE_H + BTILE_H)
#define STAGE_BYTES (STAGE_H * 2)
#define SMEM_REQ (STAGES * STAGE_BYTES)

template<int ROWS>
__device__ __forceinline__ void load_tile(const bf16* g, bf16* s, int tid, int ld) {
    int ch = tid & 7;
    int r0 = tid >> 3;
    #pragma unroll
    for (int i = 0; i < ROWS / 32; i++) {
        int r = r0 + i * 32;
        uint32_t dst = smem_u32(s + r * SROW + ch * 8);
        const bf16* src = g + (size_t)r * ld + ch * 8;
        asm volatile("cp.async.cg.shared.global [%0], [%1], 16;" :: "r"(dst), "l"(src));
    }
}

template<int EPI>
__global__ __launch_bounds__(256, 2) void mma_gemm(
    const bf16* __restrict__ A, long zA, int ldA,
    const bf16* __restrict__ B, long zB, int ldB,
    const float* __restrict__ bias,
    const float* __restrict__ res, long zR,
    void* __restrict__ Cout, long zC, int ldC,
    int K, float alpha)
{
    constexpr bool OUT_BF = (EPI == 0 || EPI == 1 || EPI == 3);
    extern __shared__ bf16 smem[];

    const int tid = threadIdx.x;
    const int m0 = blockIdx.y * BM, n0 = blockIdx.x * BN, bz = blockIdx.z;

    A += (size_t)bz * zA + (size_t)m0 * ldA;
    B += (size_t)bz * zB + (size_t)n0 * ldB;

    const int KT = K / BK;

    #pragma unroll
    for (int st = 0; st < STAGES - 1; st++) {
        load_tile<BM>(A + st * BK, smem + st * STAGE_H, tid, ldA);
        load_tile<BN>(B + st * BK, smem + st * STAGE_H + ATILE_H, tid, ldB);
        asm volatile("cp.async.commit_group;" ::: "memory");
    }

    const int lane = tid & 31, wid = tid >> 5;
    const int gid = lane >> 2, tig = lane & 3;
    const int wm = (wid & 1) * 64;
    const int wn = (wid >> 1) * 32;

    const uint32_t sbase = smem_u32(smem);
    const uint32_t a_off = ((wm + (lane & 15)) * SROW + ((lane >> 4) * 8)) * 2;
    const uint32_t b_off = (ATILE_H + (wn + (lane & 7) + ((lane >> 4) << 3)) * SROW
                            + (((lane >> 3) & 1) * 8)) * 2;

    float c[4][4][4];
    #pragma unroll
    for (int im = 0; im < 4; im++)
        #pragma unroll
        for (int in = 0; in < 4; in++)
            #pragma unroll
            for (int r = 0; r < 4; r++) c[im][in][r] = 0.f;

    uint32_t af[2][4][4], bq[2][2][4];

    for (int kt = 0; kt < KT; kt++) {
        asm volatile("cp.async.wait_group %0;" :: "n"(STAGES - 2) : "memory");
        __syncthreads();   // single barrier per kt

        if (kt + STAGES - 1 < KT) {
            int st = (kt + STAGES - 1) % STAGES;
            load_tile<BM>(A + (kt + STAGES - 1) * BK, smem + st * STAGE_H, tid, ldA);
            load_tile<BN>(B + (kt + STAGES - 1) * BK, smem + st * STAGE_H + ATILE_H, tid, ldB);
        }
        asm volatile("cp.async.commit_group;" ::: "memory");

        const uint32_t stb = sbase + (kt % STAGES) * STAGE_BYTES;

        #pragma unroll
        for (int im = 0; im < 4; im++)
            ldmatrix_x4(af[0][im], stb + a_off + im * (16 * SROW * 2));
        #pragma unroll
        for (int ib = 0; ib < 2; ib++)
            ldmatrix_x4(bq[0][ib], stb + b_off + ib * (16 * SROW * 2));

        #pragma unroll
        for (int kk = 0; kk < 4; kk++) {
            int cur = kk & 1, nxt = cur ^ 1;
            if (kk < 3) {
                const uint32_t ka = stb + (kk + 1) * 32;
                #pragma unroll
                for (int im = 0; im < 4; im++)
                    ldmatrix_x4(af[nxt][im], ka + a_off + im * (16 * SROW * 2));
                #pragma unroll
                for (int ib = 0; ib < 2; ib++)
                    ldmatrix_x4(bq[nxt][ib], ka + b_off + ib * (16 * SROW * 2));
            }
            #pragma unroll
            for (int im = 0; im < 4; im++)
                #pragma unroll
                for (int in = 0; in < 4; in++)
                    mma_bf16(c[im][in], af[cur][im], &bq[cur][in >> 1][(in & 1) * 2]);
        }
    }

    // ---- epilogue ----
    #pragma unroll
    for (int im = 0; im < 4; im++) {
        int r0 = im * 16 + gid;
        float bm0 = 0.f, bm1 = 0.f;
        if (EPI == 1 || EPI == 4) {
            bm0 = __ldg(bias + m0 + wm + r0);
            bm1 = __ldg(bias + m0 + wm + r0 + 8);
        }
        #pragma unroll
        for (int in = 0; in < 4; in++) {
            int col = in * 8 + tig * 2;
            float v0 = c[im][in][0], v1 = c[im][in][1];
            float v2 = c[im][in][2], v3 = c[im][in][3];
            if (EPI == 0) {
                float bn0 = __ldg(bias + n0 + wn + col);
                float bn1 = __ldg(bias + n0 + wn + col + 1);
                v0 += bn0; v1 += bn1; v2 += bn0; v3 += bn1;
            } else if (EPI == 1) {
                v0 += bm0; v1 += bm0; v2 += bm1; v3 += bm1;
            } else if (EPI == 2) {
                v0 *= alpha; v1 *= alpha; v2 *= alpha; v3 *= alpha;
            } else if (EPI == 4) {
                const float* ra = res + (size_t)bz * zR + (size_t)(m0 + wm + r0) * ldC + n0 + wn + col;
                const float* rb = res + (size_t)bz * zR + (size_t)(m0 + wm + r0 + 8) * ldC + n0 + wn + col;
                v0 += bm0 + ra[0]; v1 += bm0 + ra[1];
                v2 += bm1 + rb[0]; v3 += bm1 + rb[1];
            }
            if (OUT_BF) {
                bf16* Cb = (bf16*)Cout + (size_t)bz * zC + (size_t)(m0 + wm + r0) * ldC + n0 + wn + col;
                bf16* Cb2 = (bf16*)Cout + (size_t)bz * zC + (size_t)(m0 + wm + r0 + 8) * ldC + n0 + wn + col;
                *(bf162*)Cb  = __floats2bfloat162_rn(v0, v1);
                *(bf162*)Cb2 = __floats2bfloat162_rn(v2, v3);
            } else {
                float* Cf = (float*)Cout + (size_t)bz * zC + (size_t)(m0 + wm + r0) * ldC + n0 + wn + col;
                float* Cf2 = (float*)Cout + (size_t)bz * zC + (size_t)(m0 + wm + r0 + 8) * ldC + n0 + wn + col;
                *(float2*)Cf  = make_float2(v0, v1);
                *(float2*)Cf2 = make_float2(v2, v3);
            }
        }
    }
}

// ---------------- launch ----------------
extern "C" void kernel_launch(void* const* d_in, const int* in_sizes, int n_in,
                              void* d_out, int out_size)
{
    const float* x     = (const float*)d_in[0];
    const float* gamma = (const float*)d_in[1];
    const float* beta  = (const float*)d_in[2];
    const float* wq    = (const float*)d_in[3];
    const float* bq    = (const float*)d_in[4];
    const float* wk    = (const float*)d_in[5];
    const float* bk    = (const float*)d_in[6];
    const float* wv    = (const float*)d_in[7];
    const float* bv    = (const float*)d_in[8];
    const float* wo    = (const float*)d_in[9];
    const float* bo    = (const float*)d_in[10];
    float* out = (float*)d_out;

    bf16 *h16, *qk16, *v16, *ao16, *a16, *w16;
    float *s, *bqk;
    float2* part;
    cudaGetSymbolAddress((void**)&h16,  g_h16);
    cudaGetSymbolAddress((void**)&qk16, g_qk16);
    cudaGetSymbolAddress((void**)&v16,  g_v16);
    cudaGetSymbolAddress((void**)&ao16, g_ao16);
    cudaGetSymbolAddress((void**)&a16,  g_a16);
    cudaGetSymbolAddress((void**)&w16,  g_w16);
    cudaGetSymbolAddress((void**)&s,    g_s);
    cudaGetSymbolAddress((void**)&bqk,  g_bqk);
    cudaGetSymbolAddress((void**)&part, g_part);

    static bool attr_done = false;
    if (!attr_done) {
        cudaFuncSetAttribute(mma_gemm<0>, cudaFuncAttributeMaxDynamicSharedMemorySize, SMEM_REQ);
        cudaFuncSetAttribute(mma_gemm<1>, cudaFuncAttributeMaxDynamicSharedMemorySize, SMEM_REQ);
        cudaFuncSetAttribute(mma_gemm<2>, cudaFuncAttributeMaxDynamicSharedMemorySize, SMEM_REQ);
        cudaFuncSetAttribute(mma_gemm<3>, cudaFuncAttributeMaxDynamicSharedMemorySize, SMEM_REQ);
        cudaFuncSetAttribute(mma_gemm<4>, cudaFuncAttributeMaxDynamicSharedMemorySize, SMEM_REQ);
        attr_done = true;
    }

    const long CN  = (long)Cc * NN;      // [C,N] batch stride
    const long NC  = (long)NN * Cc;      // [N,C] batch stride
    const long NC2 = (long)NN * 2 * Cc;  // [N,2C] batch stride
    const long NN2 = (long)NN * NN;
    const float scale = 1.0f / sqrtf((float)Cc);

    // 1) GroupNorm (2-stage, 1024 blocks each) -> h16 [B,N,C]
    gn_stats<<<Bb * GG * 8, 256>>>(x, part);
    gn_norm <<<Bb * GG * 8, 256>>>(x, part, gamma, beta, h16);
    // 2) weights -> bf16, concat q/k biases
    round_w_kernel<<<4 * Cc * Cc / 256, 256>>>(wq, wk, wv, wo, w16);
    concat_bias_kernel<<<2 * Cc / 256, 256>>>(bq, bk, bqk);

    // 3) merged QK proj
    mma_gemm<0><<<dim3(2*Cc/BN, NN/BM, Bb), 256, SMEM_REQ>>>(
        h16, NC, Cc, w16, 0, Cc, bqk, nullptr, 0, qk16, NC2, 2*Cc, Cc, 0.f);
    // 4) V proj
    mma_gemm<1><<<dim3(NN/BN, Cc/BM, Bb), 256, SMEM_REQ>>>(
        w16 + 2*Cc*Cc, 0, Cc, h16, NC, Cc, bv, nullptr, 0, v16, CN, NN, Cc, 0.f);
    // 5) scores
    mma_gemm<2><<<dim3(NN/BN, NN/BM, Bb), 256, SMEM_REQ>>>(
        qk16, NC2, 2*Cc, qk16 + Cc, NC2, 2*Cc, nullptr, nullptr, 0, s, NN2, NN, Cc, scale);
    // 6) softmax
    softmax_kernel<<<Bb * NN, 256>>>(s, a16);
    // 7) attn * V
    mma_gemm<3><<<dim3(Cc/BN, NN/BM, Bb), 256, SMEM_REQ>>>(
        a16, NN2, NN, v16, CN, NN, nullptr, nullptr, 0, ao16, NC, Cc, NN, 0.f);
    // 8) output proj + residual
    mma_gemm<4><<<dim3(NN/BN, Cc/BM, Bb), 256, SMEM_REQ>>>(
        w16 + 3*Cc*Cc, 0, Cc, ao16, NC, Cc, bo, x, CN, out, CN, NN, Cc, 0.f);
}

// round 11
// speedup vs baseline: 1.0543x; 1.0316x over previous
#include <cuda_runtime.h>
#include <cuda_bf16.h>
#include <math.h>
#include <stdint.h>

typedef __nv_bfloat16 bf16;
typedef __nv_bfloat162 bf162;

// ---------------- problem constants ----------------
#define Bb 4
#define Cc 512
#define NN 4096
#define GG 32
#define CPG 16

// ---------------- scratch (device globals) ----------------
__device__ __align__(128) bf16  g_h16  [(size_t)Bb*NN*Cc];    // [B,N,C] GN out
__device__ __align__(128) bf16  g_qk16 [(size_t)Bb*NN*2*Cc];  // [B,N,2C] q|k
__device__ __align__(128) bf16  g_v16  [(size_t)Bb*Cc*NN];    // [B,C,N]
__device__ __align__(128) bf16  g_ao16 [(size_t)Bb*NN*Cc];    // [B,N,C]
__device__ __align__(128) bf16  g_s16  [(size_t)Bb*NN*NN];    // [B,N,N] scores bf16
__device__ __align__(128) bf16  g_a16  [(size_t)Bb*NN*NN];    // [B,N,N] attn bf16
__device__ __align__(128) bf16  g_w16  [4*Cc*Cc];             // wq|wk|wv|wo
__device__ __align__(128) float g_bqk  [2*Cc];                // bq|bk
__device__ __align__(128) float2 g_part[Bb*GG*8];             // GN partial sums

// ---------------- helpers ----------------
__device__ __forceinline__ uint32_t smem_u32(const void* p) {
    uint32_t a;
    asm("{ .reg .u64 t; cvta.to.shared.u64 t, %1; cvt.u32.u64 %0, t; }" : "=r"(a) : "l"(p));
    return a;
}
__device__ __forceinline__ void mma_bf16(float* c, const uint32_t* a, const uint32_t* b) {
    asm volatile("mma.sync.aligned.m16n8k16.row.col.f32.bf16.bf16.f32 "
        "{%0,%1,%2,%3}, {%4,%5,%6,%7}, {%8,%9}, {%0,%1,%2,%3};"
        : "+f"(c[0]), "+f"(c[1]), "+f"(c[2]), "+f"(c[3])
        : "r"(a[0]), "r"(a[1]), "r"(a[2]), "r"(a[3]), "r"(b[0]), "r"(b[1]));
}
__device__ __forceinline__ void ldmatrix_x4(uint32_t* r, uint32_t addr) {
    asm volatile("ldmatrix.sync.aligned.m8n8.x4.shared.b16 {%0,%1,%2,%3}, [%4];"
        : "=r"(r[0]), "=r"(r[1]), "=r"(r[2]), "=r"(r[3]) : "r"(addr));
}

// ---------------- block reductions ----------------
__device__ __forceinline__ float block_sum(float v, float* sh) {
    int lane = threadIdx.x & 31, w = threadIdx.x >> 5;
    #pragma unroll
    for (int o = 16; o; o >>= 1) v += __shfl_down_sync(0xffffffffu, v, o);
    if (!lane) sh[w] = v;
    __syncthreads();
    int nw = blockDim.x >> 5;
    v = (threadIdx.x < nw) ? sh[threadIdx.x] : 0.f;
    if (w == 0) {
        #pragma unroll
        for (int o = 16; o; o >>= 1) v += __shfl_down_sync(0xffffffffu, v, o);
        if (!lane) sh[0] = v;
    }
    __syncthreads();
    float r = sh[0]; __syncthreads(); return r;
}
__device__ __forceinline__ float block_max(float v, float* sh) {
    int lane = threadIdx.x & 31, w = threadIdx.x >> 5;
    #pragma unroll
    for (int o = 16; o; o >>= 1) v = fmaxf(v, __shfl_down_sync(0xffffffffu, v, o));
    if (!lane) sh[w] = v;
    __syncthreads();
    int nw = blockDim.x >> 5;
    v = (threadIdx.x < nw) ? sh[threadIdx.x] : -INFINITY;
    if (w == 0) {
        #pragma unroll
        for (int o = 16; o; o >>= 1) v = fmaxf(v, __shfl_down_sync(0xffffffffu, v, o));
        if (!lane) sh[0] = v;
    }
    __syncthreads();
    float r = sh[0]; __syncthreads(); return r;
}

// ---------------- GroupNorm stage 1: partial sums --------------------------
__global__ __launch_bounds__(256) void gn_stats(
    const float* __restrict__ x, float2* __restrict__ partials)
{
    __shared__ float sh[32];
    int blk = blockIdx.x;
    int bg = blk >> 3, p = blk & 7;
    const size_t base = (size_t)bg * CPG * NN;
    const int i0 = p * 512;

    float s = 0.f, ss = 0.f;
    #pragma unroll
    for (int c = 0; c < CPG; c++) {
        #pragma unroll
        for (int j = 0; j < 2; j++) {
            float v = x[base + (size_t)c * NN + i0 + threadIdx.x + j * 256];
            s += v; ss += v * v;
        }
    }
    s  = block_sum(s,  sh);
    ss = block_sum(ss, sh);
    if (threadIdx.x == 0) partials[blk] = make_float2(s, ss);
}

// ---------------- GroupNorm stage 2: normalize + transpose ----------------
__global__ __launch_bounds__(256) void gn_norm(
    const float* __restrict__ x, const float2* __restrict__ partials,
    const float* __restrict__ gamma, const float* __restrict__ beta,
    bf16* __restrict__ hT)
{
    int blk = blockIdx.x;
    int bg = blk >> 3, p = blk & 7;
    int b = bg / GG, g = bg % GG;

    float s = 0.f, ss = 0.f;
    #pragma unroll
    for (int q = 0; q < 8; q++) {
        float2 pr = partials[bg * 8 + q];
        s += pr.x; ss += pr.y;
    }
    const float len = (float)(CPG * NN);
    float mean = s / len;
    float inv  = rsqrtf(ss / len - mean * mean + 1e-6f);

    float gm[CPG], bt[CPG];
    #pragma unroll
    for (int c = 0; c < CPG; c++) { gm[c] = gamma[g*CPG+c] * inv; bt[c] = beta[g*CPG+c]; }

    const size_t base = (size_t)bg * CPG * NN;
    #pragma unroll
    for (int j = 0; j < 2; j++) {
        int i = p * 512 + threadIdx.x + j * 256;
        bf162 vals[CPG/2];
        #pragma unroll
        for (int c = 0; c < CPG; c += 2) {
            float a  = (x[base + (size_t)c     * NN + i] - mean) * gm[c]   + bt[c];
            float b2 = (x[base + (size_t)(c+1) * NN + i] - mean) * gm[c+1] + bt[c+1];
            vals[c/2] = __floats2bfloat162_rn(a, b2);
        }
        bf16* dst = hT + ((size_t)b * NN + i) * Cc + g * CPG;
        #pragma unroll
        for (int q = 0; q < CPG/8; q++)
            ((float4*)dst)[q] = *(float4*)&vals[q*4];
    }
}

// ---------------- weight convert + bias concat (merged) ----------------
__global__ __launch_bounds__(256) void prep_kernel(
    const float* __restrict__ a, const float* __restrict__ b,
    const float* __restrict__ c, const float* __restrict__ d,
    bf16* __restrict__ o,
    const float* __restrict__ bq, const float* __restrict__ bk,
    float* __restrict__ bqk)
{
    int i = blockIdx.x * 256 + threadIdx.x;
    int w = i >> 18, j = i & 0x3FFFF;
    const float* src = (w == 0) ? a : (w == 1) ? b : (w == 2) ? c : d;
    o[i] = __float2bfloat16_rn(src[j]);
    if (i < 2 * Cc) bqk[i] = (i < Cc) ? bq[i] : bk[i - Cc];
}

// ---------------- softmax: bf16 scores in -> bf16 attn out -------------
__global__ __launch_bounds__(256) void softmax_kernel(
    const bf16* __restrict__ s, bf16* __restrict__ a)
{
    __shared__ float sh[32];
    const uint4* p = (const uint4*)(s + (size_t)blockIdx.x * NN);
    uint4* pa = (uint4*)(a + (size_t)blockIdx.x * NN);
    // each thread: 2 uint4 = 16 bf16
    uint4 raw[2];
    float v[16];
    #pragma unroll
    for (int t = 0; t < 2; t++) raw[t] = p[threadIdx.x + t * 256];
    #pragma unroll
    for (int t = 0; t < 2; t++) {
        const uint32_t* u = (const uint32_t*)&raw[t];
        #pragma unroll
        for (int q = 0; q < 4; q++) {
            float2 f2 = __bfloat1622float2(*(const bf162*)&u[q]);
            v[t*8 + q*2]     = f2.x;
            v[t*8 + q*2 + 1] = f2.y;
        }
    }
    float m = -INFINITY;
    #pragma unroll
    for (int t = 0; t < 16; t++) m = fmaxf(m, v[t]);
    m = block_max(m, sh);
    float sum = 0.f;
    #pragma unroll
    for (int t = 0; t < 16; t++) { v[t] = __expf(v[t] - m); sum += v[t]; }
    sum = block_sum(sum, sh);
    float inv = 1.f / sum;
    uint4 outw[2];
    #pragma unroll
    for (int t = 0; t < 2; t++) {
        uint32_t* u = (uint32_t*)&outw[t];
        #pragma unroll
        for (int q = 0; q < 4; q++) {
            bf162 h = __floats2bfloat162_rn(v[t*8 + q*2] * inv, v[t*8 + q*2 + 1] * inv);
            u[q] = *(uint32_t*)&h;
        }
        pa[threadIdx.x + t * 256] = outw[t];
    }
}

// ---------------- bf16 mma.sync GEMM: D[m,n] = Σk A[m,k] B[n,k] ----------
// Round-8 config: CTA 128x128x64, 256 threads, warps 2(M)x4(N), warp 64x32.
// EPI: 0 = +bias[n] -> bf16   (merged QK proj)
//      1 = +bias[m] -> bf16   (V proj)
//      2 = *alpha  -> bf16    (scores)
//      3 = -> bf16            (attn*V)
//      4 = +bias[m]+res fp32  (output proj + residual)
#define BM 128
#define BN 128
#define BK 64
#define STAGES 3
#define SROW 72
#define ATILE_H (BM * SROW)
#define BTILE_H (BN * SROW)
#define STAGE_H (ATILE_H + BTILE_H)
#define STAGE_BYTES (STAGE_H * 2)
#define SMEM_REQ (STAGES * STAGE_BYTES)

template<int ROWS>
__device__ __forceinline__ void load_tile(const bf16* g, bf16* s, int tid, int ld) {
    int ch = tid & 7;
    int r0 = tid >> 3;
    #pragma unroll
    for (int i = 0; i < ROWS / 32; i++) {
        int r = r0 + i * 32;
        uint32_t dst = smem_u32(s + r * SROW + ch * 8);
        const bf16* src = g + (size_t)r * ld + ch * 8;
        asm volatile("cp.async.cg.shared.global [%0], [%1], 16;" :: "r"(dst), "l"(src));
    }
}

template<int EPI>
__global__ __launch_bounds__(256, 2) void mma_gemm(
    const bf16* __restrict__ A, long zA, int ldA,
    const bf16* __restrict__ B, long zB, int ldB,
    const float* __restrict__ bias,
    const float* __restrict__ res, long zR,
    void* __restrict__ Cout, long zC, int ldC,
    int K, float alpha)
{
    constexpr bool OUT_BF = (EPI != 4);
    extern __shared__ bf16 smem[];

    const int tid = threadIdx.x;
    const int m0 = blockIdx.y * BM, n0 = blockIdx.x * BN, bz = blockIdx.z;

    A += (size_t)bz * zA + (size_t)m0 * ldA;
    B += (size_t)bz * zB + (size_t)n0 * ldB;

    const int KT = K / BK;

    #pragma unroll
    for (int st = 0; st < STAGES - 1; st++) {
        load_tile<BM>(A + st * BK, smem + st * STAGE_H, tid, ldA);
        load_tile<BN>(B + st * BK, smem + st * STAGE_H + ATILE_H, tid, ldB);
        asm volatile("cp.async.commit_group;" ::: "memory");
    }

    const int lane = tid & 31, wid = tid >> 5;
    const int gid = lane >> 2, tig = lane & 3;
    const int wm = (wid & 1) * 64;
    const int wn = (wid >> 1) * 32;

    const uint32_t sbase = smem_u32(smem);
    const uint32_t a_off = ((wm + (lane & 15)) * SROW + ((lane >> 4) * 8)) * 2;
    const uint32_t b_off = (ATILE_H + (wn + (lane & 7) + ((lane >> 4) << 3)) * SROW
                            + (((lane >> 3) & 1) * 8)) * 2;

    float c[4][4][4];
    #pragma unroll
    for (int im = 0; im < 4; im++)
        #pragma unroll
        for (int in = 0; in < 4; in++)
            #pragma unroll
            for (int r = 0; r < 4; r++) c[im][in][r] = 0.f;

    uint32_t af[2][4][4], bq[2][2][4];

    for (int kt = 0; kt < KT; kt++) {
        asm volatile("cp.async.wait_group %0;" :: "n"(STAGES - 2) : "memory");
        __syncthreads();

        if (kt + STAGES - 1 < KT) {
            int st = (kt + STAGES - 1) % STAGES;
            load_tile<BM>(A + (kt + STAGES - 1) * BK, smem + st * STAGE_H, tid, ldA);
            load_tile<BN>(B + (kt + STAGES - 1) * BK, smem + st * STAGE_H + ATILE_H, tid, ldB);
        }
        asm volatile("cp.async.commit_group;" ::: "memory");

        const uint32_t stb = sbase + (kt % STAGES) * STAGE_BYTES;

        #pragma unroll
        for (int im = 0; im < 4; im++)
            ldmatrix_x4(af[0][im], stb + a_off + im * (16 * SROW * 2));
        #pragma unroll
        for (int ib = 0; ib < 2; ib++)
            ldmatrix_x4(bq[0][ib], stb + b_off + ib * (16 * SROW * 2));

        #pragma unroll
        for (int kk = 0; kk < 4; kk++) {
            int cur = kk & 1, nxt = cur ^ 1;
            if (kk < 3) {
                const uint32_t ka = stb + (kk + 1) * 32;
                #pragma unroll
                for (int im = 0; im < 4; im++)
                    ldmatrix_x4(af[nxt][im], ka + a_off + im * (16 * SROW * 2));
                #pragma unroll
                for (int ib = 0; ib < 2; ib++)
                    ldmatrix_x4(bq[nxt][ib], ka + b_off + ib * (16 * SROW * 2));
            }
            #pragma unroll
            for (int im = 0; im < 4; im++)
                #pragma unroll
                for (int in = 0; in < 4; in++)
                    mma_bf16(c[im][in], af[cur][im], &bq[cur][in >> 1][(in & 1) * 2]);
        }
    }

    // ---- epilogue ----
    #pragma unroll
    for (int im = 0; im < 4; im++) {
        int r0 = im * 16 + gid;
        float bm0 = 0.f, bm1 = 0.f;
        if (EPI == 1 || EPI == 4) {
            bm0 = __ldg(bias + m0 + wm + r0);
            bm1 = __ldg(bias + m0 + wm + r0 + 8);
        }
        #pragma unroll
        for (int in = 0; in < 4; in++) {
            int col = in * 8 + tig * 2;
            float v0 = c[im][in][0], v1 = c[im][in][1];
            float v2 = c[im][in][2], v3 = c[im][in][3];
            if (EPI == 0) {
                float bn0 = __ldg(bias + n0 + wn + col);
                float bn1 = __ldg(bias + n0 + wn + col + 1);
                v0 += bn0; v1 += bn1; v2 += bn0; v3 += bn1;
            } else if (EPI == 1) {
                v0 += bm0; v1 += bm0; v2 += bm1; v3 += bm1;
            } else if (EPI == 2) {
                v0 *= alpha; v1 *= alpha; v2 *= alpha; v3 *= alpha;
            } else if (EPI == 4) {
                const float* ra = res + (size_t)bz * zR + (size_t)(m0 + wm + r0) * ldC + n0 + wn + col;
                const float* rb = res + (size_t)bz * zR + (size_t)(m0 + wm + r0 + 8) * ldC + n0 + wn + col;
                v0 += bm0 + ra[0]; v1 += bm0 + ra[1];
                v2 += bm1 + rb[0]; v3 += bm1 + rb[1];
            }
            if (OUT_BF) {
                bf16* Cb = (bf16*)Cout + (size_t)bz * zC + (size_t)(m0 + wm + r0) * ldC + n0 + wn + col;
                bf16* Cb2 = (bf16*)Cout + (size_t)bz * zC + (size_t)(m0 + wm + r0 + 8) * ldC + n0 + wn + col;
                *(bf162*)Cb  = __floats2bfloat162_rn(v0, v1);
                *(bf162*)Cb2 = __floats2bfloat162_rn(v2, v3);
            } else {
                float* Cf = (float*)Cout + (size_t)bz * zC + (size_t)(m0 + wm + r0) * ldC + n0 + wn + col;
                float* Cf2 = (float*)Cout + (size_t)bz * zC + (size_t)(m0 + wm + r0 + 8) * ldC + n0 + wn + col;
                *(float2*)Cf  = make_float2(v0, v1);
                *(float2*)Cf2 = make_float2(v2, v3);
            }
        }
    }
}

// ---------------- launch ----------------
extern "C" void kernel_launch(void* const* d_in, const int* in_sizes, int n_in,
                              void* d_out, int out_size)
{
    const float* x     = (const float*)d_in[0];
    const float* gamma = (const float*)d_in[1];
    const float* beta  = (const float*)d_in[2];
    const float* wq    = (const float*)d_in[3];
    const float* bq    = (const float*)d_in[4];
    const float* wk    = (const float*)d_in[5];
    const float* bk    = (const float*)d_in[6];
    const float* wv    = (const float*)d_in[7];
    const float* bv    = (const float*)d_in[8];
    const float* wo    = (const float*)d_in[9];
    const float* bo    = (const float*)d_in[10];
    float* out = (float*)d_out;

    bf16 *h16, *qk16, *v16, *ao16, *s16, *a16, *w16;
    float *bqk;
    float2* part;
    cudaGetSymbolAddress((void**)&h16,  g_h16);
    cudaGetSymbolAddress((void**)&qk16, g_qk16);
    cudaGetSymbolAddress((void**)&v16,  g_v16);
    cudaGetSymbolAddress((void**)&ao16, g_ao16);
    cudaGetSymbolAddress((void**)&s16,  g_s16);
    cudaGetSymbolAddress((void**)&a16,  g_a16);
    cudaGetSymbolAddress((void**)&w16,  g_w16);
    cudaGetSymbolAddress((void**)&bqk,  g_bqk);
    cudaGetSymbolAddress((void**)&part, g_part);

    static bool attr_done = false;
    if (!attr_done) {
        cudaFuncSetAttribute(mma_gemm<0>, cudaFuncAttributeMaxDynamicSharedMemorySize, SMEM_REQ);
        cudaFuncSetAttribute(mma_gemm<1>, cudaFuncAttributeMaxDynamicSharedMemorySize, SMEM_REQ);
        cudaFuncSetAttribute(mma_gemm<2>, cudaFuncAttributeMaxDynamicSharedMemorySize, SMEM_REQ);
        cudaFuncSetAttribute(mma_gemm<3>, cudaFuncAttributeMaxDynamicSharedMemorySize, SMEM_REQ);
        cudaFuncSetAttribute(mma_gemm<4>, cudaFuncAttributeMaxDynamicSharedMemorySize, SMEM_REQ);
        attr_done = true;
    }

    const long CN  = (long)Cc * NN;
    const long NC  = (long)NN * Cc;
    const long NC2 = (long)NN * 2 * Cc;
    const long NN2 = (long)NN * NN;
    const float scale = 1.0f / sqrtf((float)Cc);

    // 1) GroupNorm (2-stage) -> h16 [B,N,C]
    gn_stats<<<Bb * GG * 8, 256>>>(x, part);
    gn_norm <<<Bb * GG * 8, 256>>>(x, part, gamma, beta, h16);
    // 2) weights -> bf16 + bias concat (merged)
    prep_kernel<<<4 * Cc * Cc / 256, 256>>>(wq, wk, wv, wo, w16, bq, bk, bqk);

    // 3) merged QK proj
    mma_gemm<0><<<dim3(2*Cc/BN, NN/BM, Bb), 256, SMEM_REQ>>>(
        h16, NC, Cc, w16, 0, Cc, bqk, nullptr, 0, qk16, NC2, 2*Cc, Cc, 0.f);
    // 4) V proj
    mma_gemm<1><<<dim3(NN/BN, Cc/BM, Bb), 256, SMEM_REQ>>>(
        w16 + 2*Cc*Cc, 0, Cc, h16, NC, Cc, bv, nullptr, 0, v16, CN, NN, Cc, 0.f);
    // 5) scores -> bf16
    mma_gemm<2><<<dim3(NN/BN, NN/BM, Bb), 256, SMEM_REQ>>>(
        qk16, NC2, 2*Cc, qk16 + Cc, NC2, 2*Cc, nullptr, nullptr, 0, s16, NN2, NN, Cc, scale);
    // 6) softmax (bf16 in, bf16 out)
    softmax_kernel<<<Bb * NN, 256>>>(s16, a16);
    // 7) attn * V
    mma_gemm<3><<<dim3(Cc/BN, NN/BM, Bb), 256, SMEM_REQ>>>(
        a16, NN2, NN, v16, CN, NN, nullptr, nullptr, 0, ao16, NC, Cc, NN, 0.f);
    // 8) output proj + residual
    mma_gemm<4><<<dim3(NN/BN, Cc/BM, Bb), 256, SMEM_REQ>>>(
        w16 + 3*Cc*Cc, 0, Cc, ao16, NC, Cc, bo, x, CN, out, CN, NN, Cc, 0.f);
}

// round 12
// speedup vs baseline: 1.0736x; 1.0183x over previous
#include <cuda_runtime.h>
#include <cuda_bf16.h>
#include <math.h>
#include <stdint.h>

typedef __nv_bfloat16 bf16;
typedef __nv_bfloat162 bf162;

// ---------------- problem constants ----------------
#define Bb 4
#define Cc 512
#define NN 4096
#define GG 32
#define CPG 16

// ---------------- scratch (device globals) ----------------
__device__ __align__(128) bf16  g_h16  [(size_t)Bb*NN*Cc];    // [B,N,C] GN out
__device__ __align__(128) bf16  g_qk16 [(size_t)Bb*NN*2*Cc];  // [B,N,2C] q|k
__device__ __align__(128) bf16  g_v16  [(size_t)Bb*Cc*NN];    // [B,C,N]
__device__ __align__(128) bf16  g_ao16 [(size_t)Bb*NN*Cc];    // [B,N,C]
__device__ __align__(128) bf16  g_e16  [(size_t)Bb*NN*NN];    // [B,N,N] exp(scores)
__device__ __align__(128) bf16  g_w16  [4*Cc*Cc];             // wq|wk|wv|wo
__device__ __align__(128) float g_bqk  [2*Cc];                // bq|bk
__device__ __align__(128) float g_rsum [Bb*NN];               // 1/rowsum [B,N]
__device__ __align__(128) float2 g_part[Bb*GG*8];             // GN partials

// ---------------- helpers ----------------
__device__ __forceinline__ uint32_t smem_u32(const void* p) {
    uint32_t a;
    asm("{ .reg .u64 t; cvta.to.shared.u64 t, %1; cvt.u32.u64 %0, t; }" : "=r"(a) : "l"(p));
    return a;
}
__device__ __forceinline__ void mma_bf16(float* c, const uint32_t* a, const uint32_t* b) {
    asm volatile("mma.sync.aligned.m16n8k16.row.col.f32.bf16.bf16.f32 "
        "{%0,%1,%2,%3}, {%4,%5,%6,%7}, {%8,%9}, {%0,%1,%2,%3};"
        : "+f"(c[0]), "+f"(c[1]), "+f"(c[2]), "+f"(c[3])
        : "r"(a[0]), "r"(a[1]), "r"(a[2]), "r"(a[3]), "r"(b[0]), "r"(b[1]));
}
__device__ __forceinline__ void ldmatrix_x4(uint32_t* r, uint32_t addr) {
    asm volatile("ldmatrix.sync.aligned.m8n8.x4.shared.b16 {%0,%1,%2,%3}, [%4];"
        : "=r"(r[0]), "=r"(r[1]), "=r"(r[2]), "=r"(r[3]) : "r"(addr));
}

// ---------------- block reduction ----------------
__device__ __forceinline__ float block_sum(float v, float* sh) {
    int lane = threadIdx.x & 31, w = threadIdx.x >> 5;
    #pragma unroll
    for (int o = 16; o; o >>= 1) v += __shfl_down_sync(0xffffffffu, v, o);
    if (!lane) sh[w] = v;
    __syncthreads();
    int nw = blockDim.x >> 5;
    v = (threadIdx.x < nw) ? sh[threadIdx.x] : 0.f;
    if (w == 0) {
        #pragma unroll
        for (int o = 16; o; o >>= 1) v += __shfl_down_sync(0xffffffffu, v, o);
        if (!lane) sh[0] = v;
    }
    __syncthreads();
    float r = sh[0]; __syncthreads(); return r;
}

// ---------------- GroupNorm stage 1 --------------------------
__global__ __launch_bounds__(256) void gn_stats(
    const float* __restrict__ x, float2* __restrict__ partials)
{
    __shared__ float sh[32];
    int blk = blockIdx.x;
    int bg = blk >> 3, p = blk & 7;
    const size_t base = (size_t)bg * CPG * NN;
    const int i0 = p * 512;

    float s = 0.f, ss = 0.f;
    #pragma unroll
    for (int c = 0; c < CPG; c++) {
        #pragma unroll
        for (int j = 0; j < 2; j++) {
            float v = x[base + (size_t)c * NN + i0 + threadIdx.x + j * 256];
            s += v; ss += v * v;
        }
    }
    s  = block_sum(s,  sh);
    ss = block_sum(ss, sh);
    if (threadIdx.x == 0) partials[blk] = make_float2(s, ss);
}

// ---------------- GroupNorm stage 2 ----------------
__global__ __launch_bounds__(256) void gn_norm(
    const float* __restrict__ x, const float2* __restrict__ partials,
    const float* __restrict__ gamma, const float* __restrict__ beta,
    bf16* __restrict__ hT)
{
    int blk = blockIdx.x;
    int bg = blk >> 3, p = blk & 7;
    int b = bg / GG, g = bg % GG;

    float s = 0.f, ss = 0.f;
    #pragma unroll
    for (int q = 0; q < 8; q++) {
        float2 pr = partials[bg * 8 + q];
        s += pr.x; ss += pr.y;
    }
    const float len = (float)(CPG * NN);
    float mean = s / len;
    float inv  = rsqrtf(ss / len - mean * mean + 1e-6f);

    float gm[CPG], bt[CPG];
    #pragma unroll
    for (int c = 0; c < CPG; c++) { gm[c] = gamma[g*CPG+c] * inv; bt[c] = beta[g*CPG+c]; }

    const size_t base = (size_t)bg * CPG * NN;
    #pragma unroll
    for (int j = 0; j < 2; j++) {
        int i = p * 512 + threadIdx.x + j * 256;
        bf162 vals[CPG/2];
        #pragma unroll
        for (int c = 0; c < CPG; c += 2) {
            float a  = (x[base + (size_t)c     * NN + i] - mean) * gm[c]   + bt[c];
            float b2 = (x[base + (size_t)(c+1) * NN + i] - mean) * gm[c+1] + bt[c+1];
            vals[c/2] = __floats2bfloat162_rn(a, b2);
        }
        bf16* dst = hT + ((size_t)b * NN + i) * Cc + g * CPG;
        #pragma unroll
        for (int q = 0; q < CPG/8; q++)
            ((float4*)dst)[q] = *(float4*)&vals[q*4];
    }
}

// ---------------- weight convert + bias concat ----------------
__global__ __launch_bounds__(256) void prep_kernel(
    const float* __restrict__ a, const float* __restrict__ b,
    const float* __restrict__ c, const float* __restrict__ d,
    bf16* __restrict__ o,
    const float* __restrict__ bq, const float* __restrict__ bk,
    float* __restrict__ bqk)
{
    int i = blockIdx.x * 256 + threadIdx.x;
    int w = i >> 18, j = i & 0x3FFFF;
    const float* src = (w == 0) ? a : (w == 1) ? b : (w == 2) ? c : d;
    o[i] = __float2bfloat16_rn(src[j]);
    if (i < 2 * Cc) bqk[i] = (i < Cc) ? bq[i] : bk[i - Cc];
}

// ---------------- rowsum of exp-scores -> 1/sum ----------------
__global__ __launch_bounds__(256) void rowsum_kernel(
    const bf16* __restrict__ e, float* __restrict__ rsum)
{
    __shared__ float sh[32];
    const uint4* p = (const uint4*)(e + (size_t)blockIdx.x * NN);
    float sum = 0.f;
    #pragma unroll
    for (int t = 0; t < 2; t++) {
        uint4 raw = p[threadIdx.x + t * 256];
        const uint32_t* u = (const uint32_t*)&raw;
        #pragma unroll
        for (int q = 0; q < 4; q++) {
            float2 f2 = __bfloat1622float2(*(const bf162*)&u[q]);
            sum += f2.x + f2.y;
        }
    }
    sum = block_sum(sum, sh);
    if (threadIdx.x == 0) rsum[blockIdx.x] = 1.f / sum;
}

// ---------------- bf16 mma.sync GEMM ----------
// EPI: 0 = +bias[n] -> bf16      (merged QK proj)
//      1 = +bias[m] -> bf16      (V proj)
//      2 = exp(v*alpha) -> bf16  (scores + softmax exp fused)
//      3 = *bias[bz*NN+m]->bf16  (attn*V, normalization fused; zBias=NN)
//      4 = +bias[m]+res fp32     (output proj + residual)
#define BM 128
#define BN 128
#define BK 64
#define STAGES 3
#define SROW 72
#define ATILE_H (BM * SROW)
#define BTILE_H (BN * SROW)
#define STAGE_H (ATILE_H + BTILE_H)
#define STAGE_BYTES (STAGE_H * 2)
#define SMEM_REQ (STAGES * STAGE_BYTES)

template<int ROWS>
__device__ __forceinline__ void load_tile(const bf16* g, bf16* s, int tid, int ld) {
    int ch = tid & 7;
    int r0 = tid >> 3;
    #pragma unroll
    for (int i = 0; i < ROWS / 32; i++) {
        int r = r0 + i * 32;
        uint32_t dst = smem_u32(s + r * SROW + ch * 8);
        const bf16* src = g + (size_t)r * ld + ch * 8;
        asm volatile("cp.async.cg.shared.global [%0], [%1], 16;" :: "r"(dst), "l"(src));
    }
}

template<int EPI>
__global__ __launch_bounds__(256, 2) void mma_gemm(
    const bf16* __restrict__ A, long zA, int ldA,
    const bf16* __restrict__ B, long zB, int ldB,
    const float* __restrict__ bias, long zBias,
    const float* __restrict__ res, long zR,
    void* __restrict__ Cout, long zC, int ldC,
    int K, float alpha)
{
    constexpr bool OUT_BF = (EPI != 4);
    extern __shared__ bf16 smem[];

    const int tid = threadIdx.x;
    const int m0 = blockIdx.y * BM, n0 = blockIdx.x * BN, bz = blockIdx.z;

    A += (size_t)bz * zA + (size_t)m0 * ldA;
    B += (size_t)bz * zB + (size_t)n0 * ldB;
    if (EPI == 1 || EPI == 3 || EPI == 4) bias += (size_t)bz * zBias;

    const int KT = K / BK;

    #pragma unroll
    for (int st = 0; st < STAGES - 1; st++) {
        load_tile<BM>(A + st * BK, smem + st * STAGE_H, tid, ldA);
        load_tile<BN>(B + st * BK, smem + st * STAGE_H + ATILE_H, tid, ldB);
        asm volatile("cp.async.commit_group;" ::: "memory");
    }

    const int lane = tid & 31, wid = tid >> 5;
    const int gid = lane >> 2, tig = lane & 3;
    const int wm = (wid & 1) * 64;
    const int wn = (wid >> 1) * 32;

    const uint32_t sbase = smem_u32(smem);
    const uint32_t a_off = ((wm + (lane & 15)) * SROW + ((lane >> 4) * 8)) * 2;
    const uint32_t b_off = (ATILE_H + (wn + (lane & 7) + ((lane >> 4) << 3)) * SROW
                            + (((lane >> 3) & 1) * 8)) * 2;

    float c[4][4][4];
    #pragma unroll
    for (int im = 0; im < 4; im++)
        #pragma unroll
        for (int in = 0; in < 4; in++)
            #pragma unroll
            for (int r = 0; r < 4; r++) c[im][in][r] = 0.f;

    uint32_t af[2][4][4], bq[2][2][4];

    for (int kt = 0; kt < KT; kt++) {
        asm volatile("cp.async.wait_group %0;" :: "n"(STAGES - 2) : "memory");
        __syncthreads();

        if (kt + STAGES - 1 < KT) {
            int st = (kt + STAGES - 1) % STAGES;
            load_tile<BM>(A + (kt + STAGES - 1) * BK, smem + st * STAGE_H, tid, ldA);
            load_tile<BN>(B + (kt + STAGES - 1) * BK, smem + st * STAGE_H + ATILE_H, tid, ldB);
        }
        asm volatile("cp.async.commit_group;" ::: "memory");

        const uint32_t stb = sbase + (kt % STAGES) * STAGE_BYTES;

        #pragma unroll
        for (int im = 0; im < 4; im++)
            ldmatrix_x4(af[0][im], stb + a_off + im * (16 * SROW * 2));
        #pragma unroll
        for (int ib = 0; ib < 2; ib++)
            ldmatrix_x4(bq[0][ib], stb + b_off + ib * (16 * SROW * 2));

        #pragma unroll
        for (int kk = 0; kk < 4; kk++) {
            int cur = kk & 1, nxt = cur ^ 1;
            if (kk < 3) {
                const uint32_t ka = stb + (kk + 1) * 32;
                #pragma unroll
                for (int im = 0; im < 4; im++)
                    ldmatrix_x4(af[nxt][im], ka + a_off + im * (16 * SROW * 2));
                #pragma unroll
                for (int ib = 0; ib < 2; ib++)
                    ldmatrix_x4(bq[nxt][ib], ka + b_off + ib * (16 * SROW * 2));
            }
            #pragma unroll
            for (int im = 0; im < 4; im++)
                #pragma unroll
                for (int in = 0; in < 4; in++)
                    mma_bf16(c[im][in], af[cur][im], &bq[cur][in >> 1][(in & 1) * 2]);
        }
    }

    // ---- epilogue ----
    #pragma unroll
    for (int im = 0; im < 4; im++) {
        int r0 = im * 16 + gid;
        float bm0 = 0.f, bm1 = 0.f;
        if (EPI == 1 || EPI == 3 || EPI == 4) {
            bm0 = __ldg(bias + m0 + wm + r0);
            bm1 = __ldg(bias + m0 + wm + r0 + 8);
        }
        #pragma unroll
        for (int in = 0; in < 4; in++) {
            int col = in * 8 + tig * 2;
            float v0 = c[im][in][0], v1 = c[im][in][1];
            float v2 = c[im][in][2], v3 = c[im][in][3];
            if (EPI == 0) {
                float bn0 = __ldg(bias + n0 + wn + col);
                float bn1 = __ldg(bias + n0 + wn + col + 1);
                v0 += bn0; v1 += bn1; v2 += bn0; v3 += bn1;
            } else if (EPI == 1) {
                v0 += bm0; v1 += bm0; v2 += bm1; v3 += bm1;
            } else if (EPI == 2) {
                v0 = __expf(v0 * alpha); v1 = __expf(v1 * alpha);
                v2 = __expf(v2 * alpha); v3 = __expf(v3 * alpha);
            } else if (EPI == 3) {
                v0 *= bm0; v1 *= bm0; v2 *= bm1; v3 *= bm1;
            } else if (EPI == 4) {
                const float* ra = res + (size_t)bz * zR + (size_t)(m0 + wm + r0) * ldC + n0 + wn + col;
                const float* rb = res + (size_t)bz * zR + (size_t)(m0 + wm + r0 + 8) * ldC + n0 + wn + col;
                v0 += bm0 + ra[0]; v1 += bm0 + ra[1];
                v2 += bm1 + rb[0]; v3 += bm1 + rb[1];
            }
            if (OUT_BF) {
                bf16* Cb = (bf16*)Cout + (size_t)bz * zC + (size_t)(m0 + wm + r0) * ldC + n0 + wn + col;
                bf16* Cb2 = (bf16*)Cout + (size_t)bz * zC + (size_t)(m0 + wm + r0 + 8) * ldC + n0 + wn + col;
                *(bf162*)Cb  = __floats2bfloat162_rn(v0, v1);
                *(bf162*)Cb2 = __floats2bfloat162_rn(v2, v3);
            } else {
                float* Cf = (float*)Cout + (size_t)bz * zC + (size_t)(m0 + wm + r0) * ldC + n0 + wn + col;
                float* Cf2 = (float*)Cout + (size_t)bz * zC + (size_t)(m0 + wm + r0 + 8) * ldC + n0 + wn + col;
                *(float2*)Cf  = make_float2(v0, v1);
                *(float2*)Cf2 = make_float2(v2, v3);
            }
        }
    }
}

// ---------------- launch ----------------
extern "C" void kernel_launch(void* const* d_in, const int* in_sizes, int n_in,
                              void* d_out, int out_size)
{
    const float* x     = (const float*)d_in[0];
    const float* gamma = (const float*)d_in[1];
    const float* beta  = (const float*)d_in[2];
    const float* wq    = (const float*)d_in[3];
    const float* bq    = (const float*)d_in[4];
    const float* wk    = (const float*)d_in[5];
    const float* bk    = (const float*)d_in[6];
    const float* wv    = (const float*)d_in[7];
    const float* bv    = (const float*)d_in[8];
    const float* wo    = (const float*)d_in[9];
    const float* bo    = (const float*)d_in[10];
    float* out = (float*)d_out;

    bf16 *h16, *qk16, *v16, *ao16, *e16, *w16;
    float *bqk, *rsum;
    float2* part;
    cudaGetSymbolAddress((void**)&h16,  g_h16);
    cudaGetSymbolAddress((void**)&qk16, g_qk16);
    cudaGetSymbolAddress((void**)&v16,  g_v16);
    cudaGetSymbolAddress((void**)&ao16, g_ao16);
    cudaGetSymbolAddress((void**)&e16,  g_e16);
    cudaGetSymbolAddress((void**)&w16,  g_w16);
    cudaGetSymbolAddress((void**)&bqk,  g_bqk);
    cudaGetSymbolAddress((void**)&rsum, g_rsum);
    cudaGetSymbolAddress((void**)&part, g_part);

    static bool attr_done = false;
    if (!attr_done) {
        cudaFuncSetAttribute(mma_gemm<0>, cudaFuncAttributeMaxDynamicSharedMemorySize, SMEM_REQ);
        cudaFuncSetAttribute(mma_gemm<1>, cudaFuncAttributeMaxDynamicSharedMemorySize, SMEM_REQ);
        cudaFuncSetAttribute(mma_gemm<2>, cudaFuncAttributeMaxDynamicSharedMemorySize, SMEM_REQ);
        cudaFuncSetAttribute(mma_gemm<3>, cudaFuncAttributeMaxDynamicSharedMemorySize, SMEM_REQ);
        cudaFuncSetAttribute(mma_gemm<4>, cudaFuncAttributeMaxDynamicSharedMemorySize, SMEM_REQ);
        attr_done = true;
    }

    const long CN  = (long)Cc * NN;
    const long NC  = (long)NN * Cc;
    const long NC2 = (long)NN * 2 * Cc;
    const long NN2 = (long)NN * NN;
    const float scale = 1.0f / sqrtf((float)Cc);

    // 1) GroupNorm (2-stage) -> h16 [B,N,C]
    gn_stats<<<Bb * GG * 8, 256>>>(x, part);
    gn_norm <<<Bb * GG * 8, 256>>>(x, part, gamma, beta, h16);
    // 2) weights -> bf16 + bias concat
    prep_kernel<<<4 * Cc * Cc / 256, 256>>>(wq, wk, wv, wo, w16, bq, bk, bqk);

    // 3) merged QK proj
    mma_gemm<0><<<dim3(2*Cc/BN, NN/BM, Bb), 256, SMEM_REQ>>>(
        h16, NC, Cc, w16, 0, Cc, bqk, 0, nullptr, 0, qk16, NC2, 2*Cc, Cc, 0.f);
    // 4) V proj (bias bv shared across batches: zBias=0)
    mma_gemm<1><<<dim3(NN/BN, Cc/BM, Bb), 256, SMEM_REQ>>>(
        w16 + 2*Cc*Cc, 0, Cc, h16, NC, Cc, bv, 0, nullptr, 0, v16, CN, NN, Cc, 0.f);
    // 5) exp-scores: e16[i,j] = exp(scale * q_i . k_j)
    mma_gemm<2><<<dim3(NN/BN, NN/BM, Bb), 256, SMEM_REQ>>>(
        qk16, NC2, 2*Cc, qk16 + Cc, NC2, 2*Cc, nullptr, 0, nullptr, 0, e16, NN2, NN, Cc, scale);
    // 6) rowsum -> 1/sum  [B*N]
    rowsum_kernel<<<Bb * NN, 256>>>(e16, rsum);
    // 7) attn*V with fused normalization (rsum per-batch stride NN)
    mma_gemm<3><<<dim3(Cc/BN, NN/BM, Bb), 256, SMEM_REQ>>>(
        e16, NN2, NN, v16, CN, NN, rsum, NN, nullptr, 0, ao16, NC, Cc, NN, 0.f);
    // 8) output proj + residual (bias bo shared: zBias=0)
    mma_gemm<4><<<dim3(NN/BN, Cc/BM, Bb), 256, SMEM_REQ>>>(
        w16 + 3*Cc*Cc, 0, Cc, ao16, NC, Cc, bo, 0, x, CN, out, CN, NN, Cc, 0.f);
}

// round 13
// speedup vs baseline: 1.0989x; 1.0236x over previous
#include <cuda_runtime.h>
#include <cuda_bf16.h>
#include <math.h>
#include <stdint.h>

typedef __nv_bfloat16 bf16;
typedef __nv_bfloat162 bf162;

// ---------------- problem constants ----------------
#define Bb 4
#define Cc 512
#define NN 4096
#define GG 32
#define CPG 16

// ---------------- scratch (device globals) ----------------
__device__ __align__(128) bf16  g_h16  [(size_t)Bb*NN*Cc];    // [B,N,C] GN out
__device__ __align__(128) bf16  g_qk16 [(size_t)Bb*NN*2*Cc];  // [B,N,2C] q|k
__device__ __align__(128) bf16  g_v16  [(size_t)Bb*Cc*NN];    // [B,C,N]
__device__ __align__(128) bf16  g_ao16 [(size_t)Bb*NN*Cc];    // [B,N,C]
__device__ __align__(128) bf16  g_e16  [(size_t)Bb*NN*NN];    // [B,N,N] exp(scores)
__device__ __align__(128) bf16  g_w16  [4*Cc*Cc];             // wq|wk|wv|wo
__device__ __align__(128) float g_bqk  [2*Cc];                // bq|bk
__device__ __align__(128) float g_rsum [Bb*NN];               // 1/rowsum [B,N]
__device__ __align__(128) float g_spart[(size_t)Bb*NN*32];    // per-CTA row partials
__device__ __align__(128) float2 g_part[Bb*GG*8];             // GN partials

// ---------------- helpers ----------------
__device__ __forceinline__ uint32_t smem_u32(const void* p) {
    uint32_t a;
    asm("{ .reg .u64 t; cvta.to.shared.u64 t, %1; cvt.u32.u64 %0, t; }" : "=r"(a) : "l"(p));
    return a;
}
__device__ __forceinline__ void mma_bf16(float* c, const uint32_t* a, const uint32_t* b) {
    asm volatile("mma.sync.aligned.m16n8k16.row.col.f32.bf16.bf16.f32 "
        "{%0,%1,%2,%3}, {%4,%5,%6,%7}, {%8,%9}, {%0,%1,%2,%3};"
        : "+f"(c[0]), "+f"(c[1]), "+f"(c[2]), "+f"(c[3])
        : "r"(a[0]), "r"(a[1]), "r"(a[2]), "r"(a[3]), "r"(b[0]), "r"(b[1]));
}
__device__ __forceinline__ void ldmatrix_x4(uint32_t* r, uint32_t addr) {
    asm volatile("ldmatrix.sync.aligned.m8n8.x4.shared.b16 {%0,%1,%2,%3}, [%4];"
        : "=r"(r[0]), "=r"(r[1]), "=r"(r[2]), "=r"(r[3]) : "r"(addr));
}

// ---------------- block reduction ----------------
__device__ __forceinline__ float block_sum(float v, float* sh) {
    int lane = threadIdx.x & 31, w = threadIdx.x >> 5;
    #pragma unroll
    for (int o = 16; o; o >>= 1) v += __shfl_down_sync(0xffffffffu, v, o);
    if (!lane) sh[w] = v;
    __syncthreads();
    int nw = blockDim.x >> 5;
    v = (threadIdx.x < nw) ? sh[threadIdx.x] : 0.f;
    if (w == 0) {
        #pragma unroll
        for (int o = 16; o; o >>= 1) v += __shfl_down_sync(0xffffffffu, v, o);
        if (!lane) sh[0] = v;
    }
    __syncthreads();
    float r = sh[0]; __syncthreads(); return r;
}

// ---------------- GroupNorm stage 1 --------------------------
__global__ __launch_bounds__(256) void gn_stats(
    const float* __restrict__ x, float2* __restrict__ partials)
{
    __shared__ float sh[32];
    int blk = blockIdx.x;
    int bg = blk >> 3, p = blk & 7;
    const size_t base = (size_t)bg * CPG * NN;
    const int i0 = p * 512;

    float s = 0.f, ss = 0.f;
    #pragma unroll
    for (int c = 0; c < CPG; c++) {
        #pragma unroll
        for (int j = 0; j < 2; j++) {
            float v = x[base + (size_t)c * NN + i0 + threadIdx.x + j * 256];
            s += v; ss += v * v;
        }
    }
    s  = block_sum(s,  sh);
    ss = block_sum(ss, sh);
    if (threadIdx.x == 0) partials[blk] = make_float2(s, ss);
}

// ---------------- GroupNorm stage 2 ----------------
__global__ __launch_bounds__(256) void gn_norm(
    const float* __restrict__ x, const float2* __restrict__ partials,
    const float* __restrict__ gamma, const float* __restrict__ beta,
    bf16* __restrict__ hT)
{
    int blk = blockIdx.x;
    int bg = blk >> 3, p = blk & 7;
    int b = bg / GG, g = bg % GG;

    float s = 0.f, ss = 0.f;
    #pragma unroll
    for (int q = 0; q < 8; q++) {
        float2 pr = partials[bg * 8 + q];
        s += pr.x; ss += pr.y;
    }
    const float len = (float)(CPG * NN);
    float mean = s / len;
    float inv  = rsqrtf(ss / len - mean * mean + 1e-6f);

    float gm[CPG], bt[CPG];
    #pragma unroll
    for (int c = 0; c < CPG; c++) { gm[c] = gamma[g*CPG+c] * inv; bt[c] = beta[g*CPG+c]; }

    const size_t base = (size_t)bg * CPG * NN;
    #pragma unroll
    for (int j = 0; j < 2; j++) {
        int i = p * 512 + threadIdx.x + j * 256;
        bf162 vals[CPG/2];
        #pragma unroll
        for (int c = 0; c < CPG; c += 2) {
            float a  = (x[base + (size_t)c     * NN + i] - mean) * gm[c]   + bt[c];
            float b2 = (x[base + (size_t)(c+1) * NN + i] - mean) * gm[c+1] + bt[c+1];
            vals[c/2] = __floats2bfloat162_rn(a, b2);
        }
        bf16* dst = hT + ((size_t)b * NN + i) * Cc + g * CPG;
        #pragma unroll
        for (int q = 0; q < CPG/8; q++)
            ((float4*)dst)[q] = *(float4*)&vals[q*4];
    }
}

// ---------------- weight convert + bias concat ----------------
__global__ __launch_bounds__(256) void prep_kernel(
    const float* __restrict__ a, const float* __restrict__ b,
    const float* __restrict__ c, const float* __restrict__ d,
    bf16* __restrict__ o,
    const float* __restrict__ bq, const float* __restrict__ bk,
    float* __restrict__ bqk)
{
    int i = blockIdx.x * 256 + threadIdx.x;
    int w = i >> 18, j = i & 0x3FFFF;
    const float* src = (w == 0) ? a : (w == 1) ? b : (w == 2) ? c : d;
    o[i] = __float2bfloat16_rn(src[j]);
    if (i < 2 * Cc) bqk[i] = (i < Cc) ? bq[i] : bk[i - Cc];
}

// ---------------- invert summed row partials (fixed order) ----------------
__global__ __launch_bounds__(256) void inv_kernel(
    const float* __restrict__ spart, float* __restrict__ rsum)
{
    int i = blockIdx.x * 256 + threadIdx.x;   // B*N = 16384 rows
    const float* p = spart + (size_t)i * 32;
    float s = 0.f;
    #pragma unroll
    for (int t = 0; t < 32; t++) s += p[t];
    rsum[i] = 1.f / s;
}

// ---------------- bf16 mma.sync GEMM ----------
// EPI: 0 = +bias[n] -> bf16       (merged QK proj)
//      1 = +bias[m] -> bf16       (V proj)
//      2 = exp(v*alpha) -> bf16 + per-CTA row-partials to spart (scores)
//      3 = *bias[bz*NN+m] -> bf16 (attn*V, normalization fused)
//      4 = +bias[m]+res fp32      (output proj + residual)
#define BM 128
#define BN 128
#define BK 64
#define STAGES 3
#define SROW 72
#define ATILE_H (BM * SROW)
#define BTILE_H (BN * SROW)
#define STAGE_H (ATILE_H + BTILE_H)
#define STAGE_BYTES (STAGE_H * 2)
#define SMEM_REQ (STAGES * STAGE_BYTES)

template<int ROWS>
__device__ __forceinline__ void load_tile(const bf16* g, bf16* s, int tid, int ld) {
    int ch = tid & 7;
    int r0 = tid >> 3;
    #pragma unroll
    for (int i = 0; i < ROWS / 32; i++) {
        int r = r0 + i * 32;
        uint32_t dst = smem_u32(s + r * SROW + ch * 8);
        const bf16* src = g + (size_t)r * ld + ch * 8;
        asm volatile("cp.async.cg.shared.global [%0], [%1], 16;" :: "r"(dst), "l"(src));
    }
}

template<int EPI>
__global__ __launch_bounds__(256, 2) void mma_gemm(
    const bf16* __restrict__ A, long zA, int ldA,
    const bf16* __restrict__ B, long zB, int ldB,
    const float* __restrict__ bias, long zBias,
    const float* __restrict__ res, long zR,
    float* __restrict__ spart,
    void* __restrict__ Cout, long zC, int ldC,
    int K, float alpha)
{
    constexpr bool OUT_BF = (EPI != 4);
    extern __shared__ bf16 smem[];

    const int tid = threadIdx.x;
    const int m0 = blockIdx.y * BM, n0 = blockIdx.x * BN, bz = blockIdx.z;

    A += (size_t)bz * zA + (size_t)m0 * ldA;
    B += (size_t)bz * zB + (size_t)n0 * ldB;
    if (EPI == 1 || EPI == 3 || EPI == 4) bias += (size_t)bz * zBias;

    const int KT = K / BK;

    #pragma unroll
    for (int st = 0; st < STAGES - 1; st++) {
        load_tile<BM>(A + st * BK, smem + st * STAGE_H, tid, ldA);
        load_tile<BN>(B + st * BK, smem + st * STAGE_H + ATILE_H, tid, ldB);
        asm volatile("cp.async.commit_group;" ::: "memory");
    }

    const int lane = tid & 31, wid = tid >> 5;
    const int gid = lane >> 2, tig = lane & 3;
    const int wm = (wid & 1) * 64;
    const int wn = (wid >> 1) * 32;

    const uint32_t sbase = smem_u32(smem);
    const uint32_t a_off = ((wm + (lane & 15)) * SROW + ((lane >> 4) * 8)) * 2;
    const uint32_t b_off = (ATILE_H + (wn + (lane & 7) + ((lane >> 4) << 3)) * SROW
                            + (((lane >> 3) & 1) * 8)) * 2;

    float c[4][4][4];
    #pragma unroll
    for (int im = 0; im < 4; im++)
        #pragma unroll
        for (int in = 0; in < 4; in++)
            #pragma unroll
            for (int r = 0; r < 4; r++) c[im][in][r] = 0.f;

    uint32_t af[2][4][4], bq[2][2][4];

    for (int kt = 0; kt < KT; kt++) {
        asm volatile("cp.async.wait_group %0;" :: "n"(STAGES - 2) : "memory");
        __syncthreads();

        if (kt + STAGES - 1 < KT) {
            int st = (kt + STAGES - 1) % STAGES;
            load_tile<BM>(A + (kt + STAGES - 1) * BK, smem + st * STAGE_H, tid, ldA);
            load_tile<BN>(B + (kt + STAGES - 1) * BK, smem + st * STAGE_H + ATILE_H, tid, ldB);
        }
        asm volatile("cp.async.commit_group;" ::: "memory");

        const uint32_t stb = sbase + (kt % STAGES) * STAGE_BYTES;

        #pragma unroll
        for (int im = 0; im < 4; im++)
            ldmatrix_x4(af[0][im], stb + a_off + im * (16 * SROW * 2));
        #pragma unroll
        for (int ib = 0; ib < 2; ib++)
            ldmatrix_x4(bq[0][ib], stb + b_off + ib * (16 * SROW * 2));

        #pragma unroll
        for (int kk = 0; kk < 4; kk++) {
            int cur = kk & 1, nxt = cur ^ 1;
            if (kk < 3) {
                const uint32_t ka = stb + (kk + 1) * 32;
                #pragma unroll
                for (int im = 0; im < 4; im++)
                    ldmatrix_x4(af[nxt][im], ka + a_off + im * (16 * SROW * 2));
                #pragma unroll
                for (int ib = 0; ib < 2; ib++)
                    ldmatrix_x4(bq[nxt][ib], ka + b_off + ib * (16 * SROW * 2));
            }
            #pragma unroll
            for (int im = 0; im < 4; im++)
                #pragma unroll
                for (int in = 0; in < 4; in++)
                    mma_bf16(c[im][in], af[cur][im], &bq[cur][in >> 1][(in & 1) * 2]);
        }
    }

    // ---- epilogue ----
    float rs[4][2];                       // EPI2 row partials (im, row-half)
    if (EPI == 2) {
        #pragma unroll
        for (int im = 0; im < 4; im++) { rs[im][0] = 0.f; rs[im][1] = 0.f; }
    }

    #pragma unroll
    for (int im = 0; im < 4; im++) {
        int r0 = im * 16 + gid;
        float bm0 = 0.f, bm1 = 0.f;
        if (EPI == 1 || EPI == 3 || EPI == 4) {
            bm0 = __ldg(bias + m0 + wm + r0);
            bm1 = __ldg(bias + m0 + wm + r0 + 8);
        }
        #pragma unroll
        for (int in = 0; in < 4; in++) {
            int col = in * 8 + tig * 2;
            float v0 = c[im][in][0], v1 = c[im][in][1];
            float v2 = c[im][in][2], v3 = c[im][in][3];
            if (EPI == 0) {
                float bn0 = __ldg(bias + n0 + wn + col);
                float bn1 = __ldg(bias + n0 + wn + col + 1);
                v0 += bn0; v1 += bn1; v2 += bn0; v3 += bn1;
            } else if (EPI == 1) {
                v0 += bm0; v1 += bm0; v2 += bm1; v3 += bm1;
            } else if (EPI == 2) {
                v0 = __expf(v0 * alpha); v1 = __expf(v1 * alpha);
                v2 = __expf(v2 * alpha); v3 = __expf(v3 * alpha);
                rs[im][0] += v0 + v1;
                rs[im][1] += v2 + v3;
            } else if (EPI == 3) {
                v0 *= bm0; v1 *= bm0; v2 *= bm1; v3 *= bm1;
            } else if (EPI == 4) {
                const float* ra = res + (size_t)bz * zR + (size_t)(m0 + wm + r0) * ldC + n0 + wn + col;
                const float* rb = res + (size_t)bz * zR + (size_t)(m0 + wm + r0 + 8) * ldC + n0 + wn + col;
                v0 += bm0 + ra[0]; v1 += bm0 + ra[1];
                v2 += bm1 + rb[0]; v3 += bm1 + rb[1];
            }
            if (OUT_BF) {
                bf16* Cb = (bf16*)Cout + (size_t)bz * zC + (size_t)(m0 + wm + r0) * ldC + n0 + wn + col;
                bf16* Cb2 = (bf16*)Cout + (size_t)bz * zC + (size_t)(m0 + wm + r0 + 8) * ldC + n0 + wn + col;
                *(bf162*)Cb  = __floats2bfloat162_rn(v0, v1);
                *(bf162*)Cb2 = __floats2bfloat162_rn(v2, v3);
            } else {
                float* Cf = (float*)Cout + (size_t)bz * zC + (size_t)(m0 + wm + r0) * ldC + n0 + wn + col;
                float* Cf2 = (float*)Cout + (size_t)bz * zC + (size_t)(m0 + wm + r0 + 8) * ldC + n0 + wn + col;
                *(float2*)Cf  = make_float2(v0, v1);
                *(float2*)Cf2 = make_float2(v2, v3);
            }
        }
    }

    // ---- EPI2: deterministic per-CTA row-sum reduction -> spart ----
    if (EPI == 2) {
        __syncthreads();                              // smem free after mainloop
        float* srow = (float*)smem;                   // [4 n-warps][128 rows]
        const int nwIdx = wid >> 1;
        #pragma unroll
        for (int im = 0; im < 4; im++) {
            #pragma unroll
            for (int h = 0; h < 2; h++) {
                float v = rs[im][h];
                v += __shfl_xor_sync(0xffffffffu, v, 1);
                v += __shfl_xor_sync(0xffffffffu, v, 2);
                if (tig == 0)
                    srow[nwIdx * 128 + wm + im * 16 + gid + h * 8] = v;
            }
        }
        __syncthreads();
        if (tid < 128) {
            float t = srow[tid] + srow[128 + tid] + srow[256 + tid] + srow[384 + tid];
            spart[((size_t)bz * NN + m0 + tid) * 32 + blockIdx.x] = t;
        }
    }
}

// ---------------- launch ----------------
extern "C" void kernel_launch(void* const* d_in, const int* in_sizes, int n_in,
                              void* d_out, int out_size)
{
    const float* x     = (const float*)d_in[0];
    const float* gamma = (const float*)d_in[1];
    const float* beta  = (const float*)d_in[2];
    const float* wq    = (const float*)d_in[3];
    const float* bq    = (const float*)d_in[4];
    const float* wk    = (const float*)d_in[5];
    const float* bk    = (const float*)d_in[6];
    const float* wv    = (const float*)d_in[7];
    const float* bv    = (const float*)d_in[8];
    const float* wo    = (const float*)d_in[9];
    const float* bo    = (const float*)d_in[10];
    float* out = (float*)d_out;

    bf16 *h16, *qk16, *v16, *ao16, *e16, *w16;
    float *bqk, *rsum, *spart;
    float2* part;
    cudaGetSymbolAddress((void**)&h16,  g_h16);
    cudaGetSymbolAddress((void**)&qk16, g_qk16);
    cudaGetSymbolAddress((void**)&v16,  g_v16);
    cudaGetSymbolAddress((void**)&ao16, g_ao16);
    cudaGetSymbolAddress((void**)&e16,  g_e16);
    cudaGetSymbolAddress((void**)&w16,  g_w16);
    cudaGetSymbolAddress((void**)&bqk,  g_bqk);
    cudaGetSymbolAddress((void**)&rsum, g_rsum);
    cudaGetSymbolAddress((void**)&spart, g_spart);
    cudaGetSymbolAddress((void**)&part, g_part);

    static bool attr_done = false;
    if (!attr_done) {
        cudaFuncSetAttribute(mma_gemm<0>, cudaFuncAttributeMaxDynamicSharedMemorySize, SMEM_REQ);
        cudaFuncSetAttribute(mma_gemm<1>, cudaFuncAttributeMaxDynamicSharedMemorySize, SMEM_REQ);
        cudaFuncSetAttribute(mma_gemm<2>, cudaFuncAttributeMaxDynamicSharedMemorySize, SMEM_REQ);
        cudaFuncSetAttribute(mma_gemm<3>, cudaFuncAttributeMaxDynamicSharedMemorySize, SMEM_REQ);
        cudaFuncSetAttribute(mma_gemm<4>, cudaFuncAttributeMaxDynamicSharedMemorySize, SMEM_REQ);
        attr_done = true;
    }

    const long CN  = (long)Cc * NN;
    const long NC  = (long)NN * Cc;
    const long NC2 = (long)NN * 2 * Cc;
    const long NN2 = (long)NN * NN;
    const float scale = 1.0f / sqrtf((float)Cc);

    // 1) GroupNorm (2-stage) -> h16 [B,N,C]
    gn_stats<<<Bb * GG * 8, 256>>>(x, part);
    gn_norm <<<Bb * GG * 8, 256>>>(x, part, gamma, beta, h16);
    // 2) weights -> bf16 + bias concat
    prep_kernel<<<4 * Cc * Cc / 256, 256>>>(wq, wk, wv, wo, w16, bq, bk, bqk);

    // 3) merged QK proj
    mma_gemm<0><<<dim3(2*Cc/BN, NN/BM, Bb), 256, SMEM_REQ>>>(
        h16, NC, Cc, w16, 0, Cc, bqk, 0, nullptr, 0, nullptr, qk16, NC2, 2*Cc, Cc, 0.f);
    // 4) V proj
    mma_gemm<1><<<dim3(NN/BN, Cc/BM, Bb), 256, SMEM_REQ>>>(
        w16 + 2*Cc*Cc, 0, Cc, h16, NC, Cc, bv, 0, nullptr, 0, nullptr, v16, CN, NN, Cc, 0.f);
    // 5) exp-scores + fused per-CTA row partials
    mma_gemm<2><<<dim3(NN/BN, NN/BM, Bb), 256, SMEM_REQ>>>(
        qk16, NC2, 2*Cc, qk16 + Cc, NC2, 2*Cc, nullptr, 0, nullptr, 0, spart, e16, NN2, NN, Cc, scale);
    // 6) invert summed partials -> 1/rowsum  (2 MB read)
    inv_kernel<<<Bb * NN / 256, 256>>>(spart, rsum);
    // 7) attn*V with fused normalization
    mma_gemm<3><<<dim3(Cc/BN, NN/BM, Bb), 256, SMEM_REQ>>>(
        e16, NN2, NN, v16, CN, NN, rsum, NN, nullptr, 0, nullptr, ao16, NC, Cc, NN, 0.f);
    // 8) output proj + residual
    mma_gemm<4><<<dim3(NN/BN, Cc/BM, Bb), 256, SMEM_REQ>>>(
        w16 + 3*Cc*Cc, 0, Cc, ao16, NC, Cc, bo, 0, x, CN, nullptr, out, CN, NN, Cc, 0.f);
}

// round 14
// speedup vs baseline: 1.1083x; 1.0085x over previous
#include <cuda_runtime.h>
#include <cuda_bf16.h>
#include <math.h>
#include <stdint.h>

typedef __nv_bfloat16 bf16;
typedef __nv_bfloat162 bf162;

// ---------------- problem constants ----------------
#define Bb 4
#define Cc 512
#define NN 4096
#define GG 32
#define CPG 16

// ---------------- scratch (device globals) ----------------
__device__ __align__(128) bf16  g_h16  [(size_t)Bb*NN*Cc];    // [B,N,C] GN out
__device__ __align__(128) bf16  g_qk16 [(size_t)Bb*NN*2*Cc];  // [B,N,2C] q|k
__device__ __align__(128) bf16  g_v16  [(size_t)Bb*Cc*NN];    // [B,C,N]
__device__ __align__(128) bf16  g_ao16 [(size_t)Bb*NN*Cc];    // [B,N,C]
__device__ __align__(128) bf16  g_e16  [(size_t)Bb*NN*NN];    // [B,N,N] exp(scores)
__device__ __align__(128) bf16  g_w16  [4*Cc*Cc];             // wq|wk|wv|wo
__device__ __align__(128) float g_bqk  [2*Cc];                // bq|bk
__device__ __align__(128) float g_spart[(size_t)Bb*NN*32];    // per-CTA row partials
__device__ __align__(128) float2 g_part[Bb*GG*8];             // GN partials

// ---------------- helpers ----------------
__device__ __forceinline__ uint32_t smem_u32(const void* p) {
    uint32_t a;
    asm("{ .reg .u64 t; cvta.to.shared.u64 t, %1; cvt.u32.u64 %0, t; }" : "=r"(a) : "l"(p));
    return a;
}
__device__ __forceinline__ void mma_bf16(float* c, const uint32_t* a, const uint32_t* b) {
    asm volatile("mma.sync.aligned.m16n8k16.row.col.f32.bf16.bf16.f32 "
        "{%0,%1,%2,%3}, {%4,%5,%6,%7}, {%8,%9}, {%0,%1,%2,%3};"
        : "+f"(c[0]), "+f"(c[1]), "+f"(c[2]), "+f"(c[3])
        : "r"(a[0]), "r"(a[1]), "r"(a[2]), "r"(a[3]), "r"(b[0]), "r"(b[1]));
}
__device__ __forceinline__ void ldmatrix_x4(uint32_t* r, uint32_t addr) {
    asm volatile("ldmatrix.sync.aligned.m8n8.x4.shared.b16 {%0,%1,%2,%3}, [%4];"
        : "=r"(r[0]), "=r"(r[1]), "=r"(r[2]), "=r"(r[3]) : "r"(addr));
}

// ---------------- block reduction ----------------
__device__ __forceinline__ float block_sum(float v, float* sh) {
    int lane = threadIdx.x & 31, w = threadIdx.x >> 5;
    #pragma unroll
    for (int o = 16; o; o >>= 1) v += __shfl_down_sync(0xffffffffu, v, o);
    if (!lane) sh[w] = v;
    __syncthreads();
    int nw = blockDim.x >> 5;
    v = (threadIdx.x < nw) ? sh[threadIdx.x] : 0.f;
    if (w == 0) {
        #pragma unroll
        for (int o = 16; o; o >>= 1) v += __shfl_down_sync(0xffffffffu, v, o);
        if (!lane) sh[0] = v;
    }
    __syncthreads();
    float r = sh[0]; __syncthreads(); return r;
}

// ---------------- GroupNorm stage 1 --------------------------
__global__ __launch_bounds__(256) void gn_stats(
    const float* __restrict__ x, float2* __restrict__ partials)
{
    __shared__ float sh[32];
    int blk = blockIdx.x;
    int bg = blk >> 3, p = blk & 7;
    const size_t base = (size_t)bg * CPG * NN;
    const int i0 = p * 512;

    float s = 0.f, ss = 0.f;
    #pragma unroll
    for (int c = 0; c < CPG; c++) {
        #pragma unroll
        for (int j = 0; j < 2; j++) {
            float v = x[base + (size_t)c * NN + i0 + threadIdx.x + j * 256];
            s += v; ss += v * v;
        }
    }
    s  = block_sum(s,  sh);
    ss = block_sum(ss, sh);
    if (threadIdx.x == 0) partials[blk] = make_float2(s, ss);
}

// ---------------- GroupNorm stage 2 ----------------
__global__ __launch_bounds__(256) void gn_norm(
    const float* __restrict__ x, const float2* __restrict__ partials,
    const float* __restrict__ gamma, const float* __restrict__ beta,
    bf16* __restrict__ hT)
{
    int blk = blockIdx.x;
    int bg = blk >> 3, p = blk & 7;
    int b = bg / GG, g = bg % GG;

    float s = 0.f, ss = 0.f;
    #pragma unroll
    for (int q = 0; q < 8; q++) {
        float2 pr = partials[bg * 8 + q];
        s += pr.x; ss += pr.y;
    }
    const float len = (float)(CPG * NN);
    float mean = s / len;
    float inv  = rsqrtf(ss / len - mean * mean + 1e-6f);

    float gm[CPG], bt[CPG];
    #pragma unroll
    for (int c = 0; c < CPG; c++) { gm[c] = gamma[g*CPG+c] * inv; bt[c] = beta[g*CPG+c]; }

    const size_t base = (size_t)bg * CPG * NN;
    #pragma unroll
    for (int j = 0; j < 2; j++) {
        int i = p * 512 + threadIdx.x + j * 256;
        bf162 vals[CPG/2];
        #pragma unroll
        for (int c = 0; c < CPG; c += 2) {
            float a  = (x[base + (size_t)c     * NN + i] - mean) * gm[c]   + bt[c];
            float b2 = (x[base + (size_t)(c+1) * NN + i] - mean) * gm[c+1] + bt[c+1];
            vals[c/2] = __floats2bfloat162_rn(a, b2);
        }
        bf16* dst = hT + ((size_t)b * NN + i) * Cc + g * CPG;
        #pragma unroll
        for (int q = 0; q < CPG/8; q++)
            ((float4*)dst)[q] = *(float4*)&vals[q*4];
    }
}

// ---------------- weight convert + bias concat ----------------
__global__ __launch_bounds__(256) void prep_kernel(
    const float* __restrict__ a, const float* __restrict__ b,
    const float* __restrict__ c, const float* __restrict__ d,
    bf16* __restrict__ o,
    const float* __restrict__ bq, const float* __restrict__ bk,
    float* __restrict__ bqk)
{
    int i = blockIdx.x * 256 + threadIdx.x;
    int w = i >> 18, j = i & 0x3FFFF;
    const float* src = (w == 0) ? a : (w == 1) ? b : (w == 2) ? c : d;
    o[i] = __float2bfloat16_rn(src[j]);
    if (i < 2 * Cc) bqk[i] = (i < Cc) ? bq[i] : bk[i - Cc];
}

// ---------------- bf16 mma.sync GEMM ----------
// EPI: 0 = +bias[n] -> bf16       (merged QK proj)
//      1 = +bias[m] -> bf16       (V proj)
//      2 = exp(v*alpha) -> bf16 + per-CTA row partials -> spart (scores)
//      3 = *invsum[m] -> bf16     (attn*V; invsum computed in-kernel from spart)
//      4 = +bias[m]+res fp32      (output proj + residual)
#define BM 128
#define BN 128
#define BK 64
#define STAGES 3
#define SROW 72
#define ATILE_H (BM * SROW)
#define BTILE_H (BN * SROW)
#define STAGE_H (ATILE_H + BTILE_H)
#define STAGE_BYTES (STAGE_H * 2)
#define SMEM_REQ (STAGES * STAGE_BYTES + 512)   // +512B rsum slab (EPI3)

template<int ROWS>
__device__ __forceinline__ void load_tile(const bf16* g, bf16* s, int tid, int ld) {
    int ch = tid & 7;
    int r0 = tid >> 3;
    #pragma unroll
    for (int i = 0; i < ROWS / 32; i++) {
        int r = r0 + i * 32;
        uint32_t dst = smem_u32(s + r * SROW + ch * 8);
        const bf16* src = g + (size_t)r * ld + ch * 8;
        asm volatile("cp.async.cg.shared.global [%0], [%1], 16;" :: "r"(dst), "l"(src));
    }
}

template<int EPI>
__global__ __launch_bounds__(256, 2) void mma_gemm(
    const bf16* __restrict__ A, long zA, int ldA,
    const bf16* __restrict__ B, long zB, int ldB,
    const float* __restrict__ bias, long zBias,
    const float* __restrict__ res, long zR,
    float* __restrict__ spart,
    void* __restrict__ Cout, long zC, int ldC,
    int K, float alpha)
{
    constexpr bool OUT_BF = (EPI != 4);
    extern __shared__ bf16 smem[];
    float* srsum = (float*)(smem + STAGES * STAGE_H);   // 128 floats (EPI3)

    const int tid = threadIdx.x;
    const int m0 = blockIdx.y * BM, n0 = blockIdx.x * BN, bz = blockIdx.z;

    A += (size_t)bz * zA + (size_t)m0 * ldA;
    B += (size_t)bz * zB + (size_t)n0 * ldB;
    if (EPI == 1 || EPI == 4) bias += (size_t)bz * zBias;

    const int KT = K / BK;

    #pragma unroll
    for (int st = 0; st < STAGES - 1; st++) {
        load_tile<BM>(A + st * BK, smem + st * STAGE_H, tid, ldA);
        load_tile<BN>(B + st * BK, smem + st * STAGE_H + ATILE_H, tid, ldB);
        asm volatile("cp.async.commit_group;" ::: "memory");
    }

    // EPI3: fixed-order inverse row-sums from spart into smem (overlaps fills).
    // Ordered vs epilogue reads by the kt-loop __syncthreads.
    if (EPI == 3) {
        if (tid < 128) {
            const float* p = spart + ((size_t)bz * NN + m0 + tid) * 32;
            float s = 0.f;
            #pragma unroll
            for (int t = 0; t < 32; t++) s += p[t];
            srsum[tid] = 1.f / s;
        }
    }

    const int lane = tid & 31, wid = tid >> 5;
    const int gid = lane >> 2, tig = lane & 3;
    const int wm = (wid & 1) * 64;
    const int wn = (wid >> 1) * 32;

    const uint32_t sbase = smem_u32(smem);
    const uint32_t a_off = ((wm + (lane & 15)) * SROW + ((lane >> 4) * 8)) * 2;
    const uint32_t b_off = (ATILE_H + (wn + (lane & 7) + ((lane >> 4) << 3)) * SROW
                            + (((lane >> 3) & 1) * 8)) * 2;

    float c[4][4][4];
    #pragma unroll
    for (int im = 0; im < 4; im++)
        #pragma unroll
        for (int in = 0; in < 4; in++)
            #pragma unroll
            for (int r = 0; r < 4; r++) c[im][in][r] = 0.f;

    uint32_t af[2][4][4], bq[2][2][4];

    for (int kt = 0; kt < KT; kt++) {
        asm volatile("cp.async.wait_group %0;" :: "n"(STAGES - 2) : "memory");
        __syncthreads();

        if (kt + STAGES - 1 < KT) {
            int st = (kt + STAGES - 1) % STAGES;
            load_tile<BM>(A + (kt + STAGES - 1) * BK, smem + st * STAGE_H, tid, ldA);
            load_tile<BN>(B + (kt + STAGES - 1) * BK, smem + st * STAGE_H + ATILE_H, tid, ldB);
        }
        asm volatile("cp.async.commit_group;" ::: "memory");

        const uint32_t stb = sbase + (kt % STAGES) * STAGE_BYTES;

        #pragma unroll
        for (int im = 0; im < 4; im++)
            ldmatrix_x4(af[0][im], stb + a_off + im * (16 * SROW * 2));
        #pragma unroll
        for (int ib = 0; ib < 2; ib++)
            ldmatrix_x4(bq[0][ib], stb + b_off + ib * (16 * SROW * 2));

        #pragma unroll
        for (int kk = 0; kk < 4; kk++) {
            int cur = kk & 1, nxt = cur ^ 1;
            if (kk < 3) {
                const uint32_t ka = stb + (kk + 1) * 32;
                #pragma unroll
                for (int im = 0; im < 4; im++)
                    ldmatrix_x4(af[nxt][im], ka + a_off + im * (16 * SROW * 2));
                #pragma unroll
                for (int ib = 0; ib < 2; ib++)
                    ldmatrix_x4(bq[nxt][ib], ka + b_off + ib * (16 * SROW * 2));
            }
            #pragma unroll
            for (int im = 0; im < 4; im++)
                #pragma unroll
                for (int in = 0; in < 4; in++)
                    mma_bf16(c[im][in], af[cur][im], &bq[cur][in >> 1][(in & 1) * 2]);
        }
    }

    // ---- epilogue ----
    float rs[4][2];
    if (EPI == 2) {
        #pragma unroll
        for (int im = 0; im < 4; im++) { rs[im][0] = 0.f; rs[im][1] = 0.f; }
    }

    #pragma unroll
    for (int im = 0; im < 4; im++) {
        int r0 = im * 16 + gid;
        float bm0 = 0.f, bm1 = 0.f;
        if (EPI == 1 || EPI == 4) {
            bm0 = __ldg(bias + m0 + wm + r0);
            bm1 = __ldg(bias + m0 + wm + r0 + 8);
        } else if (EPI == 3) {
            bm0 = srsum[wm + r0];
            bm1 = srsum[wm + r0 + 8];
        }
        #pragma unroll
        for (int in = 0; in < 4; in++) {
            int col = in * 8 + tig * 2;
            float v0 = c[im][in][0], v1 = c[im][in][1];
            float v2 = c[im][in][2], v3 = c[im][in][3];
            if (EPI == 0) {
                float bn0 = __ldg(bias + n0 + wn + col);
                float bn1 = __ldg(bias + n0 + wn + col + 1);
                v0 += bn0; v1 += bn1; v2 += bn0; v3 += bn1;
            } else if (EPI == 1) {
                v0 += bm0; v1 += bm0; v2 += bm1; v3 += bm1;
            } else if (EPI == 2) {
                v0 = __expf(v0 * alpha); v1 = __expf(v1 * alpha);
                v2 = __expf(v2 * alpha); v3 = __expf(v3 * alpha);
                rs[im][0] += v0 + v1;
                rs[im][1] += v2 + v3;
            } else if (EPI == 3) {
                v0 *= bm0; v1 *= bm0; v2 *= bm1; v3 *= bm1;
            } else if (EPI == 4) {
                const float* ra = res + (size_t)bz * zR + (size_t)(m0 + wm + r0) * ldC + n0 + wn + col;
                const float* rb = res + (size_t)bz * zR + (size_t)(m0 + wm + r0 + 8) * ldC + n0 + wn + col;
                v0 += bm0 + ra[0]; v1 += bm0 + ra[1];
                v2 += bm1 + rb[0]; v3 += bm1 + rb[1];
            }
            if (OUT_BF) {
                bf16* Cb = (bf16*)Cout + (size_t)bz * zC + (size_t)(m0 + wm + r0) * ldC + n0 + wn + col;
                bf16* Cb2 = (bf16*)Cout + (size_t)bz * zC + (size_t)(m0 + wm + r0 + 8) * ldC + n0 + wn + col;
                *(bf162*)Cb  = __floats2bfloat162_rn(v0, v1);
                *(bf162*)Cb2 = __floats2bfloat162_rn(v2, v3);
            } else {
                float* Cf = (float*)Cout + (size_t)bz * zC + (size_t)(m0 + wm + r0) * ldC + n0 + wn + col;
                float* Cf2 = (float*)Cout + (size_t)bz * zC + (size_t)(m0 + wm + r0 + 8) * ldC + n0 + wn + col;
                *(float2*)Cf  = make_float2(v0, v1);
                *(float2*)Cf2 = make_float2(v2, v3);
            }
        }
    }

    // ---- EPI2: deterministic per-CTA row-sum reduction -> spart ----
    if (EPI == 2) {
        __syncthreads();
        float* srow = (float*)smem;
        const int nwIdx = wid >> 1;
        #pragma unroll
        for (int im = 0; im < 4; im++) {
            #pragma unroll
            for (int h = 0; h < 2; h++) {
                float v = rs[im][h];
                v += __shfl_xor_sync(0xffffffffu, v, 1);
                v += __shfl_xor_sync(0xffffffffu, v, 2);
                if (tig == 0)
                    srow[nwIdx * 128 + wm + im * 16 + gid + h * 8] = v;
            }
        }
        __syncthreads();
        if (tid < 128) {
            float t = srow[tid] + srow[128 + tid] + srow[256 + tid] + srow[384 + tid];
            spart[((size_t)bz * NN + m0 + tid) * 32 + blockIdx.x] = t;
        }
    }
}

// ---------------- launch ----------------
extern "C" void kernel_launch(void* const* d_in, const int* in_sizes, int n_in,
                              void* d_out, int out_size)
{
    const float* x     = (const float*)d_in[0];
    const float* gamma = (const float*)d_in[1];
    const float* beta  = (const float*)d_in[2];
    const float* wq    = (const float*)d_in[3];
    const float* bq    = (const float*)d_in[4];
    const float* wk    = (const float*)d_in[5];
    const float* bk    = (const float*)d_in[6];
    const float* wv    = (const float*)d_in[7];
    const float* bv    = (const float*)d_in[8];
    const float* wo    = (const float*)d_in[9];
    const float* bo    = (const float*)d_in[10];
    float* out = (float*)d_out;

    bf16 *h16, *qk16, *v16, *ao16, *e16, *w16;
    float *bqk, *spart;
    float2* part;
    cudaGetSymbolAddress((void**)&h16,  g_h16);
    cudaGetSymbolAddress((void**)&qk16, g_qk16);
    cudaGetSymbolAddress((void**)&v16,  g_v16);
    cudaGetSymbolAddress((void**)&ao16, g_ao16);
    cudaGetSymbolAddress((void**)&e16,  g_e16);
    cudaGetSymbolAddress((void**)&w16,  g_w16);
    cudaGetSymbolAddress((void**)&bqk,  g_bqk);
    cudaGetSymbolAddress((void**)&spart, g_spart);
    cudaGetSymbolAddress((void**)&part, g_part);

    static bool attr_done = false;
    if (!attr_done) {
        cudaFuncSetAttribute(mma_gemm<0>, cudaFuncAttributeMaxDynamicSharedMemorySize, SMEM_REQ);
        cudaFuncSetAttribute(mma_gemm<1>, cudaFuncAttributeMaxDynamicSharedMemorySize, SMEM_REQ);
        cudaFuncSetAttribute(mma_gemm<2>, cudaFuncAttributeMaxDynamicSharedMemorySize, SMEM_REQ);
        cudaFuncSetAttribute(mma_gemm<3>, cudaFuncAttributeMaxDynamicSharedMemorySize, SMEM_REQ);
        cudaFuncSetAttribute(mma_gemm<4>, cudaFuncAttributeMaxDynamicSharedMemorySize, SMEM_REQ);
        attr_done = true;
    }

    const long CN  = (long)Cc * NN;
    const long NC  = (long)NN * Cc;
    const long NC2 = (long)NN * 2 * Cc;
    const long NN2 = (long)NN * NN;
    const float scale = 1.0f / sqrtf((float)Cc);

    // PDL attribute: tail-overlap with the PREVIOUS (independent) kernel.
    cudaLaunchAttribute pdl[1];
    pdl[0].id = cudaLaunchAttributeProgrammaticStreamSerialization;
    pdl[0].val.programmaticStreamSerializationAllowed = 1;

    // 1) GroupNorm (2-stage) -> h16 [B,N,C]
    gn_stats<<<Bb * GG * 8, 256>>>(x, part);
    gn_norm <<<Bb * GG * 8, 256>>>(x, part, gamma, beta, h16);

    // 2) prep (independent of GN) — PDL overlap with gn_norm tail
    {
        cudaLaunchConfig_t cfg = {};
        cfg.gridDim = dim3(4 * Cc * Cc / 256);
        cfg.blockDim = dim3(256);
        cfg.stream = 0;
        cfg.attrs = pdl; cfg.numAttrs = 1;
        cudaLaunchKernelEx(&cfg, prep_kernel, wq, wk, wv, wo, w16, bq, bk, bqk);
    }

    // 3) merged QK proj (depends on gn_norm + prep — normal launch)
    mma_gemm<0><<<dim3(2*Cc/BN, NN/BM, Bb), 256, SMEM_REQ>>>(
        h16, NC, Cc, w16, 0, Cc, bqk, 0, nullptr, 0, nullptr, qk16, NC2, 2*Cc, Cc, 0.f);

    // 4) V proj (independent of QK proj) — PDL overlap with gemm0 tail
    {
        cudaLaunchConfig_t cfg = {};
        cfg.gridDim = dim3(NN/BN, Cc/BM, Bb);
        cfg.blockDim = dim3(256);
        cfg.dynamicSmemBytes = SMEM_REQ;
        cfg.stream = 0;
        cfg.attrs = pdl; cfg.numAttrs = 1;
        cudaLaunchKernelEx(&cfg, mma_gemm<1>,
            (const bf16*)(w16 + 2*Cc*Cc), 0L, (int)Cc,
            (const bf16*)h16, NC, (int)Cc,
            bv, 0L, (const float*)nullptr, 0L, (float*)nullptr,
            (void*)v16, CN, (int)NN, (int)Cc, 0.f);
    }

    // 5) exp-scores + fused per-CTA row partials
    mma_gemm<2><<<dim3(NN/BN, NN/BM, Bb), 256, SMEM_REQ>>>(
        qk16, NC2, 2*Cc, qk16 + Cc, NC2, 2*Cc, nullptr, 0, nullptr, 0, spart, e16, NN2, NN, Cc, scale);
    // 6) attn*V with in-kernel inverse rowsum (from spart) + normalization
    mma_gemm<3><<<dim3(Cc/BN, NN/BM, Bb), 256, SMEM_REQ>>>(
        e16, NN2, NN, v16, CN, NN, nullptr, 0, nullptr, 0, spart, ao16, NC, Cc, NN, 0.f);
    // 7) output proj + residual
    mma_gemm<4><<<dim3(NN/BN, Cc/BM, Bb), 256, SMEM_REQ>>>(
        w16 + 3*Cc*Cc, 0, Cc, ao16, NC, Cc, bo, 0, x, CN, nullptr, out, CN, NN, Cc, 0.f);
}